// round 2
// baseline (speedup 1.0000x reference)
#include <cuda_runtime.h>
#include <math.h>

// Problem constants
#define FDIM 64
#define HDIM 128
#define TILE_E 64
#define NTHREADS 256

// Shared memory layout (floats):
//  sW1   [64*128]   = 8192
//  sW2   [128*64]   = 8192
//  sWrr  [64*128]   = 8192
//  sWrc  [128*128]  = 16384
//  biases 128+64+128+128 = 448
//  sX    [64*64]    = 4096   (x, later t)
//  sH    [64*128]   = 8192   (h1, later u)
//  ints: sObs[64], sJ[64]
#define SMEM_FLOATS (8192*3 + 16384 + 448 + 4096 + 8192)
#define SMEM_BYTES  (SMEM_FLOATS*4 + 128*4)

__device__ __forceinline__ float gelu_f(float x) {
    // exact erf-based GELU (matches torch nn.GELU default / jax approximate=False)
    return 0.5f * x * (1.0f + erff(x * 0.70710678118654752440f));
}

// C-tile: 8 edges x 4 cols per thread, N=128 wide. A stride = K.
template <int K>
__device__ __forceinline__ void mm_n128(const float* __restrict__ A,
                                        const float* __restrict__ W,
                                        int e0, int c0, float acc[8][4]) {
    #pragma unroll
    for (int i = 0; i < 8; i++) { acc[i][0]=0.f; acc[i][1]=0.f; acc[i][2]=0.f; acc[i][3]=0.f; }
    #pragma unroll 2
    for (int k = 0; k < K; k += 2) {
        float4 w0 = *(const float4*)(W + k * 128 + c0);
        float4 w1 = *(const float4*)(W + (k + 1) * 128 + c0);
        #pragma unroll
        for (int i = 0; i < 8; i++) {
            float2 a = *(const float2*)(A + (e0 + i) * K + k);
            acc[i][0] = fmaf(a.y, w1.x, fmaf(a.x, w0.x, acc[i][0]));
            acc[i][1] = fmaf(a.y, w1.y, fmaf(a.x, w0.y, acc[i][1]));
            acc[i][2] = fmaf(a.y, w1.z, fmaf(a.x, w0.z, acc[i][2]));
            acc[i][3] = fmaf(a.y, w1.w, fmaf(a.x, w0.w, acc[i][3]));
        }
    }
}

// C-tile: 8 edges x 2 cols per thread, N=64 wide, K=128, A stride = 128.
__device__ __forceinline__ void mm_n64_k128(const float* __restrict__ A,
                                            const float* __restrict__ W,
                                            int e0, int c0, float acc[8][2]) {
    #pragma unroll
    for (int i = 0; i < 8; i++) { acc[i][0]=0.f; acc[i][1]=0.f; }
    #pragma unroll 2
    for (int k = 0; k < 128; k += 2) {
        float2 w0 = *(const float2*)(W + k * 64 + c0);
        float2 w1 = *(const float2*)(W + (k + 1) * 64 + c0);
        #pragma unroll
        for (int i = 0; i < 8; i++) {
            float2 a = *(const float2*)(A + (e0 + i) * 128 + k);
            acc[i][0] = fmaf(a.y, w1.x, fmaf(a.x, w0.x, acc[i][0]));
            acc[i][1] = fmaf(a.y, w1.y, fmaf(a.x, w0.y, acc[i][1]));
        }
    }
}

__global__ void __launch_bounds__(NTHREADS, 1)
attr_rel_kernel(const float* __restrict__ known_mask,
                const int*   __restrict__ obs_idx,
                const int*   __restrict__ obs_mask_idx,
                const int*   __restrict__ attr_idx,
                const float* __restrict__ obs_embs,
                const float* __restrict__ fea_corr,
                const float* __restrict__ W1,  const float* __restrict__ b1,
                const float* __restrict__ W2,  const float* __restrict__ b2,
                const float* __restrict__ Wrr, const float* __restrict__ brr,
                const float* __restrict__ Wrc, const float* __restrict__ brc,
                float* __restrict__ out, int E)
{
    extern __shared__ float smem[];
    float* sW1  = smem;
    float* sW2  = sW1  + 8192;
    float* sWrr = sW2  + 8192;
    float* sWrc = sWrr + 8192;
    float* sb1  = sWrc + 16384;
    float* sb2  = sb1  + 128;
    float* sbrr = sb2  + 64;
    float* sbrc = sbrr + 128;
    float* sX   = sbrc + 128;        // 64x64
    float* sH   = sX   + 64 * 64;    // 64x128
    int*   sObs = (int*)(sH + 64 * 128);
    int*   sJ   = sObs + 64;

    const int tid  = threadIdx.x;
    const int warp = tid >> 5;
    const int lane = tid & 31;

    // ---- one-time cooperative weight load ----
    for (int i = tid; i < 8192 / 4;  i += NTHREADS) ((float4*)sW1 )[i] = ((const float4*)W1 )[i];
    for (int i = tid; i < 8192 / 4;  i += NTHREADS) ((float4*)sW2 )[i] = ((const float4*)W2 )[i];
    for (int i = tid; i < 8192 / 4;  i += NTHREADS) ((float4*)sWrr)[i] = ((const float4*)Wrr)[i];
    for (int i = tid; i < 16384 / 4; i += NTHREADS) ((float4*)sWrc)[i] = ((const float4*)Wrc)[i];
    for (int i = tid; i < 128; i += NTHREADS) sb1[i]  = b1[i];
    for (int i = tid; i < 64;  i += NTHREADS) sb2[i]  = b2[i];
    for (int i = tid; i < 128; i += NTHREADS) sbrr[i] = brr[i];
    for (int i = tid; i < 128; i += NTHREADS) sbrc[i] = brc[i];
    __syncthreads();

    const int ntiles = (E + TILE_E - 1) / TILE_E;

    for (int tile = blockIdx.x; tile < ntiles; tile += gridDim.x) {
        const int base = tile * TILE_E;
        const int n_e  = min(TILE_E, E - base);

        // ---- stage 0: gather indices; X = softmax(m_i * m_j) in closed form ----
        {
            const int e = tid >> 2;         // edge within tile (0..63)
            const int q = tid & 3;          // quadrant: 16 features each
            const int eg = (e < n_e) ? base + e : base;
            const int row = obs_mask_idx[eg];
            const int j   = attr_idx[eg];
            if (q == 0) { sObs[e] = obs_idx[eg]; sJ[e] = j; }
            const float* mrow = known_mask + (long)row * FDIM;
            float mv[16];
            float s = 0.f;
            #pragma unroll
            for (int t = 0; t < 4; t++) {
                float4 v = *(const float4*)(mrow + q * 16 + t * 4);
                mv[t*4+0]=v.x; mv[t*4+1]=v.y; mv[t*4+2]=v.z; mv[t*4+3]=v.w;
                s += v.x + v.y + v.z + v.w;
            }
            // reduce partial sums over the 4 threads of this edge (consecutive lanes)
            s += __shfl_xor_sync(0xffffffffu, s, 1);
            s += __shfl_xor_sync(0xffffffffu, s, 2);
            const float kones = s - mrow[j];                 // ones with attr pos zeroed
            const float EULER = 2.71828182845904523536f;
            const float denom = kones * EULER + (64.0f - kones);
            const float alpha = 1.0f / denom;                // softmax value at zeros
            const float beta  = EULER * alpha;               // softmax value at ones
            #pragma unroll
            for (int t = 0; t < 16; t++) {
                const int f = q * 16 + t;
                sX[e * FDIM + f] = (mv[t] != 0.0f && f != j) ? beta : alpha;
            }
        }
        __syncthreads();

        // ---- stage 1: H = gelu(X @ W1 + b1)   [64x64]x[64x128] ----
        {
            const int e0 = warp * 8, c0 = lane * 4;
            float acc[8][4];
            mm_n128<64>(sX, sW1, e0, c0, acc);
            const float4 bb = *(const float4*)(sb1 + c0);
            #pragma unroll
            for (int i = 0; i < 8; i++) {
                float4 r;
                r.x = gelu_f(acc[i][0] + bb.x);
                r.y = gelu_f(acc[i][1] + bb.y);
                r.z = gelu_f(acc[i][2] + bb.z);
                r.w = gelu_f(acc[i][3] + bb.w);
                *(float4*)(sH + (e0 + i) * HDIM + c0) = r;
            }
        }
        __syncthreads();

        // ---- stage 2: t = fea_corr[j] * gelu(H @ W2 + b2)  -> sX ----
        {
            const int e0 = warp * 8, c0 = lane * 2;
            float acc[8][2];
            mm_n64_k128(sH, sW2, e0, c0, acc);
            const float2 bb = *(const float2*)(sb2 + c0);
            #pragma unroll
            for (int i = 0; i < 8; i++) {
                const int j = sJ[e0 + i];
                const float2 fc = *(const float2*)(fea_corr + j * FDIM + c0);
                float2 r;
                r.x = gelu_f(acc[i][0] + bb.x) * fc.x;
                r.y = gelu_f(acc[i][1] + bb.y) * fc.y;
                *(float2*)(sX + (e0 + i) * FDIM + c0) = r;
            }
        }
        __syncthreads();

        // ---- stage 3: U = obs_h * gelu(t @ Wrr + brr) -> sH ----
        {
            const int e0 = warp * 8, c0 = lane * 4;
            float acc[8][4];
            mm_n128<64>(sX, sWrr, e0, c0, acc);
            const float4 bb = *(const float4*)(sbrr + c0);
            #pragma unroll
            for (int i = 0; i < 8; i++) {
                const long oi = sObs[e0 + i];
                const float4 oh = *(const float4*)(obs_embs + oi * HDIM + c0);
                float4 r;
                r.x = gelu_f(acc[i][0] + bb.x) * oh.x;
                r.y = gelu_f(acc[i][1] + bb.y) * oh.y;
                r.z = gelu_f(acc[i][2] + bb.z) * oh.z;
                r.w = gelu_f(acc[i][3] + bb.w) * oh.w;
                *(float4*)(sH + (e0 + i) * HDIM + c0) = r;
            }
        }
        __syncthreads();

        // ---- stage 4: out = gelu(U @ Wrc + brc) -> global ----
        {
            const int e0 = warp * 8, c0 = lane * 4;
            float acc[8][4];
            mm_n128<128>(sH, sWrc, e0, c0, acc);
            const float4 bb = *(const float4*)(sbrc + c0);
            #pragma unroll
            for (int i = 0; i < 8; i++) {
                if (e0 + i < n_e) {
                    float4 r;
                    r.x = gelu_f(acc[i][0] + bb.x);
                    r.y = gelu_f(acc[i][1] + bb.y);
                    r.z = gelu_f(acc[i][2] + bb.z);
                    r.w = gelu_f(acc[i][3] + bb.w);
                    *(float4*)(out + (long)(base + e0 + i) * HDIM + c0) = r;
                }
            }
        }
        __syncthreads();
    }
}

extern "C" void kernel_launch(void* const* d_in, const int* in_sizes, int n_in,
                              void* d_out, int out_size) {
    const float* known_mask   = (const float*)d_in[0];
    const int*   obs_idx      = (const int*)  d_in[1];
    const int*   obs_mask_idx = (const int*)  d_in[2];
    const int*   attr_idx     = (const int*)  d_in[3];
    const float* obs_embs     = (const float*)d_in[4];
    const float* fea_corr     = (const float*)d_in[5];
    const float* W1  = (const float*)d_in[6];
    const float* b1  = (const float*)d_in[7];
    const float* W2  = (const float*)d_in[8];
    const float* b2  = (const float*)d_in[9];
    const float* Wrr = (const float*)d_in[10];
    const float* brr = (const float*)d_in[11];
    const float* Wrc = (const float*)d_in[12];
    const float* brc = (const float*)d_in[13];
    const int E = in_sizes[1];

    int sms = 148;
    cudaDeviceGetAttribute(&sms, cudaDevAttrMultiProcessorCount, 0);
    cudaFuncSetAttribute(attr_rel_kernel,
                         cudaFuncAttributeMaxDynamicSharedMemorySize, SMEM_BYTES);

    attr_rel_kernel<<<sms, NTHREADS, SMEM_BYTES>>>(
        known_mask, obs_idx, obs_mask_idx, attr_idx, obs_embs, fea_corr,
        W1, b1, W2, b2, Wrr, brr, Wrc, brc,
        (float*)d_out, E);
}

// round 7
// speedup vs baseline: 2.3691x; 2.3691x over previous
#include <cuda_runtime.h>
#include <math.h>
#include <stdint.h>

#define NTHREADS 256
#define TILE_E   64

// ---------------- smem layout (bytes) ----------------
#define OFF_W1F   0         // W1  frags [64x128]  32768
#define OFF_W2F   32768     // W2  frags [128x64]  32768
#define OFF_WRRF  65536     // Wrr frags [64x128]  32768
#define OFF_WRCF  98304     // Wrc frags [128x128] 65536
#define OFF_A0    163840    // acts X/T: 64 x 68 floats = 17408
#define OFF_A1    181248    // acts H/U: 64 x 132 floats = 33792
#define OFF_B1    215040    // 128 f
#define OFF_B2    215552    // 64 f
#define OFF_BRR   215808    // 128 f
#define OFF_BRC   216320    // 128 f
#define OFF_OBS   216832    // 64 int
#define OFF_J     217088    // 64 int
#define SMEM_BYTES 217344

#define STR0 68    // float stride of A0 (K=64 buffer), conflict-free: bank=(4r+c)%32
#define STR1 132   // float stride of A1 (K=128 buffer)

__device__ __forceinline__ float gelu_f(float x) {
    return 0.5f * x * (1.0f + erff(x * 0.70710678118654752440f));
}

__device__ __forceinline__ uint32_t f2tf(float x) {
    uint32_t r;
    asm("cvt.rna.tf32.f32 %0, %1;" : "=r"(r) : "f"(x));
    return r;
}

__device__ __forceinline__ void mma8(float d[4], uint32_t a0, uint32_t a1,
                                     uint32_t a2, uint32_t a3,
                                     uint32_t b0, uint32_t b1) {
    asm volatile(
        "mma.sync.aligned.m16n8k8.row.col.f32.tf32.tf32.f32 "
        "{%0,%1,%2,%3}, {%4,%5,%6,%7}, {%8,%9}, {%0,%1,%2,%3};"
        : "+f"(d[0]), "+f"(d[1]), "+f"(d[2]), "+f"(d[3])
        : "r"(a0), "r"(a1), "r"(a2), "r"(a3), "r"(b0), "r"(b1));
}

// MMA sweep: M=16 rows at m0, NT n-tiles starting at nt0, K8 k-steps.
// A: row-major padded smem acts; Wf: fragment-ordered weights.
template <int K8, int NT, int STRIDE>
__device__ __forceinline__ void run_mma(const uint32_t* __restrict__ A, int m0,
                                        const uint32_t* __restrict__ Wf, int nt0,
                                        int lane, float acc[NT][4]) {
    const int r = lane >> 2, c = lane & 3;
    #pragma unroll
    for (int j = 0; j < NT; j++) { acc[j][0]=0.f; acc[j][1]=0.f; acc[j][2]=0.f; acc[j][3]=0.f; }
    const uint32_t* a0p = A + (m0 + r) * STRIDE + c;
    const uint32_t* a1p = A + (m0 + r + 8) * STRIDE + c;
    #pragma unroll
    for (int ks = 0; ks < K8; ks++) {
        const uint32_t a0 = a0p[ks*8];
        const uint32_t a2 = a0p[ks*8 + 4];
        const uint32_t a1 = a1p[ks*8];
        const uint32_t a3 = a1p[ks*8 + 4];
        #pragma unroll
        for (int j = 0; j < NT; j++) {
            const uint2 b = *(const uint2*)(Wf + (((nt0 + j) * K8 + ks) << 6) + lane * 2);
            mma8(acc[j], a0, a1, a2, a3, b.x, b.y);
        }
    }
}

// W global [K,N] row-major -> tf32 B-fragment order:
// dst[((nt*K8+ks)*64 + lane*2 + reg)] = tf32(W[(ks*8 + lane%4 + reg*4) * N + nt*8 + lane/4])
__device__ __forceinline__ void prep_frag(const float* __restrict__ W, int K, int N,
                                          uint32_t* __restrict__ dst, int tid) {
    const int K8 = K >> 3;
    for (int j = tid; j < K * N; j += NTHREADS) {
        const int reg  = j & 1;
        const int lane = (j >> 1) & 31;
        const int fk   = j >> 6;
        const int ks   = fk % K8;
        const int nt   = fk / K8;
        const int k = ks * 8 + (lane & 3) + reg * 4;
        const int n = nt * 8 + (lane >> 2);
        dst[j] = f2tf(W[k * N + n]);
    }
}

__global__ void __launch_bounds__(NTHREADS, 1)
attr_rel_mma(const float* __restrict__ km,  const int* __restrict__ obsI,
             const int* __restrict__ omI,   const int* __restrict__ atI,
             const float* __restrict__ obsE, const float* __restrict__ fcorr,
             const float* __restrict__ W1,  const float* __restrict__ b1,
             const float* __restrict__ W2,  const float* __restrict__ b2,
             const float* __restrict__ Wrr, const float* __restrict__ brr,
             const float* __restrict__ Wrc, const float* __restrict__ brc,
             float* __restrict__ out, int E)
{
    extern __shared__ char smem[];
    uint32_t* W1f  = (uint32_t*)(smem + OFF_W1F);
    uint32_t* W2f  = (uint32_t*)(smem + OFF_W2F);
    uint32_t* Wrrf = (uint32_t*)(smem + OFF_WRRF);
    uint32_t* Wrcf = (uint32_t*)(smem + OFF_WRCF);
    uint32_t* A0   = (uint32_t*)(smem + OFF_A0);
    uint32_t* A1   = (uint32_t*)(smem + OFF_A1);
    float* sb1  = (float*)(smem + OFF_B1);
    float* sb2  = (float*)(smem + OFF_B2);
    float* sbrr = (float*)(smem + OFF_BRR);
    float* sbrc = (float*)(smem + OFF_BRC);
    int* sObs = (int*)(smem + OFF_OBS);
    int* sJ   = (int*)(smem + OFF_J);

    const int tid  = threadIdx.x;
    const int warp = tid >> 5;
    const int lane = tid & 31;
    const int wm   = warp & 3;       // M group: edges [wm*16, wm*16+16)
    const int wn   = warp >> 2;      // N half
    const int m0   = wm * 16;
    const int r    = lane >> 2;
    const int q    = lane & 3;

    // ---- one-time weight prep (fragment order, tf32-rounded) ----
    prep_frag(W1,   64, 128, W1f,  tid);
    prep_frag(W2,  128,  64, W2f,  tid);
    prep_frag(Wrr,  64, 128, Wrrf, tid);
    prep_frag(Wrc, 128, 128, Wrcf, tid);
    for (int i = tid; i < 128; i += NTHREADS) sb1[i]  = b1[i];
    for (int i = tid; i < 64;  i += NTHREADS) sb2[i]  = b2[i];
    for (int i = tid; i < 128; i += NTHREADS) sbrr[i] = brr[i];
    for (int i = tid; i < 128; i += NTHREADS) sbrc[i] = brc[i];
    __syncthreads();

    const int ntiles = (E + TILE_E - 1) / TILE_E;

    for (int tile = blockIdx.x; tile < ntiles; tile += gridDim.x) {
        const int base = tile * TILE_E;
        const int n_e  = min(TILE_E, E - base);

        // ---- stage 0: X = softmax(m_i*m_j) closed form -> A0 (tf32 bits) ----
        {
            const int e  = tid >> 2;          // edge in tile
            const int qq = tid & 3;           // 16-feature quadrant
            const int eg = base + (e < n_e ? e : n_e - 1);
            const int mrowi = omI[eg];
            const int jj    = atI[eg];
            if (qq == 0) { sObs[e] = obsI[eg]; sJ[e] = jj; }
            const float* mrow = km + (size_t)mrowi * 64;
            float mv[16];
            float s = 0.f;
            #pragma unroll
            for (int t = 0; t < 4; t++) {
                float4 v = *(const float4*)(mrow + qq * 16 + t * 4);
                mv[t*4+0]=v.x; mv[t*4+1]=v.y; mv[t*4+2]=v.z; mv[t*4+3]=v.w;
                s += v.x + v.y + v.z + v.w;
            }
            s += __shfl_xor_sync(0xffffffffu, s, 1);
            s += __shfl_xor_sync(0xffffffffu, s, 2);
            const float kn = s - mrow[jj];
            const float EU = 2.71828182845904523536f;
            const float alpha = 1.f / (kn * EU + (64.f - kn));
            const uint32_t ua = f2tf(alpha);
            const uint32_t ub = f2tf(EU * alpha);
            uint32_t w[16];
            #pragma unroll
            for (int t = 0; t < 16; t++) {
                const int f = qq * 16 + t;
                w[t] = (mv[t] != 0.f && f != jj) ? ub : ua;
            }
            uint4* dst = (uint4*)(A0 + e * STR0 + qq * 16);
            dst[0] = make_uint4(w[0],  w[1],  w[2],  w[3]);
            dst[1] = make_uint4(w[4],  w[5],  w[6],  w[7]);
            dst[2] = make_uint4(w[8],  w[9],  w[10], w[11]);
            dst[3] = make_uint4(w[12], w[13], w[14], w[15]);
        }
        __syncthreads();

        // ---- stage 1: H = gelu(X @ W1 + b1) -> A1   (K=64, N=128) ----
        {
            float acc[8][4];
            run_mma<8, 8, STR0>(A0, m0, W1f, wn * 8, lane, acc);
            #pragma unroll
            for (int j = 0; j < 8; j++) {
                const int n0 = (wn * 8 + j) * 8 + 2 * q;
                const float2 bb = *(const float2*)(sb1 + n0);
                uint2 lo, hi;
                lo.x = f2tf(gelu_f(acc[j][0] + bb.x));
                lo.y = f2tf(gelu_f(acc[j][1] + bb.y));
                hi.x = f2tf(gelu_f(acc[j][2] + bb.x));
                hi.y = f2tf(gelu_f(acc[j][3] + bb.y));
                *(uint2*)(A1 + (m0 + r) * STR1 + n0)     = lo;
                *(uint2*)(A1 + (m0 + r + 8) * STR1 + n0) = hi;
            }
        }
        __syncthreads();

        // ---- stage 2: T = fea_corr[j] * gelu(H @ W2 + b2) -> A0   (K=128, N=64) ----
        {
            float acc[4][4];
            run_mma<16, 4, STR1>(A1, m0, W2f, wn * 4, lane, acc);
            const int e0 = m0 + r, e1 = e0 + 8;
            const int j0 = sJ[e0], j1 = sJ[e1];
            #pragma unroll
            for (int j = 0; j < 4; j++) {
                const int n0 = (wn * 4 + j) * 8 + 2 * q;
                const float2 bb = *(const float2*)(sb2 + n0);
                const float2 f0 = __ldg((const float2*)(fcorr + (size_t)j0 * 64 + n0));
                const float2 f1 = __ldg((const float2*)(fcorr + (size_t)j1 * 64 + n0));
                uint2 lo, hi;
                lo.x = f2tf(f0.x * gelu_f(acc[j][0] + bb.x));
                lo.y = f2tf(f0.y * gelu_f(acc[j][1] + bb.y));
                hi.x = f2tf(f1.x * gelu_f(acc[j][2] + bb.x));
                hi.y = f2tf(f1.y * gelu_f(acc[j][3] + bb.y));
                *(uint2*)(A0 + e0 * STR0 + n0) = lo;
                *(uint2*)(A0 + e1 * STR0 + n0) = hi;
            }
        }
        __syncthreads();

        // ---- stage 3: U = obs_h * gelu(T @ Wrr + brr) -> A1   (K=64, N=128) ----
        {
            float acc[8][4];
            run_mma<8, 8, STR0>(A0, m0, Wrrf, wn * 8, lane, acc);
            const int e0 = m0 + r, e1 = e0 + 8;
            const size_t o0 = (size_t)sObs[e0] * 128;
            const size_t o1 = (size_t)sObs[e1] * 128;
            #pragma unroll
            for (int j = 0; j < 8; j++) {
                const int n0 = (wn * 8 + j) * 8 + 2 * q;
                const float2 bb = *(const float2*)(sbrr + n0);
                const float2 v0 = __ldg((const float2*)(obsE + o0 + n0));
                const float2 v1 = __ldg((const float2*)(obsE + o1 + n0));
                uint2 lo, hi;
                lo.x = f2tf(v0.x * gelu_f(acc[j][0] + bb.x));
                lo.y = f2tf(v0.y * gelu_f(acc[j][1] + bb.y));
                hi.x = f2tf(v1.x * gelu_f(acc[j][2] + bb.x));
                hi.y = f2tf(v1.y * gelu_f(acc[j][3] + bb.y));
                *(uint2*)(A1 + e0 * STR1 + n0) = lo;
                *(uint2*)(A1 + e1 * STR1 + n0) = hi;
            }
        }
        __syncthreads();

        // ---- stage 4: out = gelu(U @ Wrc + brc) -> global   (K=128, N=128) ----
        {
            float acc[8][4];
            run_mma<16, 8, STR1>(A1, m0, Wrcf, wn * 8, lane, acc);
            const int e0 = m0 + r, e1 = e0 + 8;
            float* o0 = out + (size_t)(base + e0) * 128;
            float* o1 = out + (size_t)(base + e1) * 128;
            #pragma unroll
            for (int j = 0; j < 8; j++) {
                const int n0 = (wn * 8 + j) * 8 + 2 * q;
                const float2 bb = *(const float2*)(sbrc + n0);
                if (e0 < n_e) {
                    float2 v;
                    v.x = gelu_f(acc[j][0] + bb.x);
                    v.y = gelu_f(acc[j][1] + bb.y);
                    *(float2*)(o0 + n0) = v;
                }
                if (e1 < n_e) {
                    float2 v;
                    v.x = gelu_f(acc[j][2] + bb.x);
                    v.y = gelu_f(acc[j][3] + bb.y);
                    *(float2*)(o1 + n0) = v;
                }
            }
        }
        __syncthreads();   // protects sObs/sJ/A0 before next tile's stage 0
    }
}

extern "C" void kernel_launch(void* const* d_in, const int* in_sizes, int n_in,
                              void* d_out, int out_size) {
    const float* known_mask   = (const float*)d_in[0];
    const int*   obs_idx      = (const int*)  d_in[1];
    const int*   obs_mask_idx = (const int*)  d_in[2];
    const int*   attr_idx     = (const int*)  d_in[3];
    const float* obs_embs     = (const float*)d_in[4];
    const float* fea_corr     = (const float*)d_in[5];
    const float* W1  = (const float*)d_in[6];
    const float* b1  = (const float*)d_in[7];
    const float* W2  = (const float*)d_in[8];
    const float* b2  = (const float*)d_in[9];
    const float* Wrr = (const float*)d_in[10];
    const float* brr = (const float*)d_in[11];
    const float* Wrc = (const float*)d_in[12];
    const float* brc = (const float*)d_in[13];
    const int E = in_sizes[1];

    int sms = 148;
    cudaDeviceGetAttribute(&sms, cudaDevAttrMultiProcessorCount, 0);
    cudaFuncSetAttribute(attr_rel_mma,
                         cudaFuncAttributeMaxDynamicSharedMemorySize, SMEM_BYTES);

    attr_rel_mma<<<sms, NTHREADS, SMEM_BYTES>>>(
        known_mask, obs_idx, obs_mask_idx, attr_idx, obs_embs, fea_corr,
        W1, b1, W2, b2, Wrr, brr, Wrc, brc,
        (float*)d_out, E);
}

// round 8
// speedup vs baseline: 2.3994x; 1.0128x over previous
#include <cuda_runtime.h>
#include <math.h>
#include <stdint.h>

#define NTHREADS 256
#define TILE_E   64

// ---------------- smem layout (bytes) ----------------
#define OFF_W1F   0         // W1  frags [64x128]  32768
#define OFF_W2F   32768     // W2  frags [128x64]  32768
#define OFF_WRRF  65536     // Wrr frags [64x128]  32768
#define OFF_WRCF  98304     // Wrc frags [128x128] 65536
#define OFF_A0    163840    // acts X/T: 64 x 68 floats = 17408
#define OFF_A1    181248    // acts H/U: 64 x 132 floats = 33792
#define OFF_B1    215040    // 128 f
#define OFF_B2    215552    // 64 f
#define OFF_BRR   215808    // 128 f
#define OFF_BRC   216320    // 128 f
#define OFF_OBS   216832    // 64 int
#define OFF_J     217088    // 64 int
#define SMEM_BYTES 217344

#define STR0 68    // float stride of A0 (K=64 buffer): bank=(4r+c)%32, conflict-free
#define STR1 132   // float stride of A1 (K=128 buffer)

__device__ __forceinline__ float gelu_f(float x) {
    return 0.5f * x * (1.0f + erff(x * 0.70710678118654752440f));
}

__device__ __forceinline__ uint32_t f2tf(float x) {
    uint32_t r;
    asm("cvt.rna.tf32.f32 %0, %1;" : "=r"(r) : "f"(x));
    return r;
}

__device__ __forceinline__ void mma8(float d[4], uint32_t a0, uint32_t a1,
                                     uint32_t a2, uint32_t a3,
                                     uint32_t b0, uint32_t b1) {
    asm volatile(
        "mma.sync.aligned.m16n8k8.row.col.f32.tf32.tf32.f32 "
        "{%0,%1,%2,%3}, {%4,%5,%6,%7}, {%8,%9}, {%0,%1,%2,%3};"
        : "+f"(d[0]), "+f"(d[1]), "+f"(d[2]), "+f"(d[3])
        : "r"(a0), "r"(a1), "r"(a2), "r"(a3), "r"(b0), "r"(b1));
}

// W global [K,N] row-major -> tf32 B-fragment order:
// dst[((nt*K8+ks)*64 + lane*2 + reg)] = tf32(W[(ks*8 + lane%4 + reg*4) * N + nt*8 + lane/4])
__device__ __forceinline__ void prep_frag(const float* __restrict__ W, int K, int N,
                                          uint32_t* __restrict__ dst, int tid) {
    const int K8 = K >> 3;
    for (int j = tid; j < K * N; j += NTHREADS) {
        const int reg  = j & 1;
        const int lane = (j >> 1) & 31;
        const int fk   = j >> 6;
        const int ks   = fk % K8;
        const int nt   = fk / K8;
        const int k = ks * 8 + (lane & 3) + reg * 4;
        const int n = nt * 8 + (lane >> 2);
        dst[j] = f2tf(W[k * N + n]);
    }
}

__global__ void __launch_bounds__(NTHREADS, 1)
attr_rel_mma(const float* __restrict__ km,  const int* __restrict__ obsI,
             const int* __restrict__ omI,   const int* __restrict__ atI,
             const float* __restrict__ obsE, const float* __restrict__ fcorr,
             const float* __restrict__ W1,  const float* __restrict__ b1,
             const float* __restrict__ W2,  const float* __restrict__ b2,
             const float* __restrict__ Wrr, const float* __restrict__ brr,
             const float* __restrict__ Wrc, const float* __restrict__ brc,
             float* __restrict__ out, int E)
{
    extern __shared__ char smem[];
    uint32_t* W1f  = (uint32_t*)(smem + OFF_W1F);
    uint32_t* W2f  = (uint32_t*)(smem + OFF_W2F);
    uint32_t* Wrrf = (uint32_t*)(smem + OFF_WRRF);
    uint32_t* Wrcf = (uint32_t*)(smem + OFF_WRCF);
    uint32_t* A0   = (uint32_t*)(smem + OFF_A0);
    uint32_t* A1   = (uint32_t*)(smem + OFF_A1);
    float* sb1  = (float*)(smem + OFF_B1);
    float* sb2  = (float*)(smem + OFF_B2);
    float* sbrr = (float*)(smem + OFF_BRR);
    float* sbrc = (float*)(smem + OFF_BRC);
    int* sObs = (int*)(smem + OFF_OBS);
    int* sJ   = (int*)(smem + OFF_J);

    const int tid  = threadIdx.x;
    const int warp = tid >> 5;
    const int lane = tid & 31;
    const int wm   = warp & 1;       // M group: edges [wm*32, wm*32+32)
    const int wn   = warp >> 1;      // N group (0..3)
    const int r    = lane >> 2;
    const int q    = lane & 3;

    // ---- one-time weight prep (fragment order, tf32-rounded) ----
    prep_frag(W1,   64, 128, W1f,  tid);
    prep_frag(W2,  128,  64, W2f,  tid);
    prep_frag(Wrr,  64, 128, Wrrf, tid);
    prep_frag(Wrc, 128, 128, Wrcf, tid);
    for (int i = tid; i < 128; i += NTHREADS) sb1[i]  = b1[i];
    for (int i = tid; i < 64;  i += NTHREADS) sb2[i]  = b2[i];
    for (int i = tid; i < 128; i += NTHREADS) sbrr[i] = brr[i];
    for (int i = tid; i < 128; i += NTHREADS) sbrc[i] = brc[i];
    __syncthreads();

    // ---- persistent register cache of stage-1 / stage-3 B fragments ----
    uint2 B1c[32], B3c[32];
    #pragma unroll
    for (int nt = 0; nt < 4; nt++)
        #pragma unroll
        for (int ks = 0; ks < 8; ks++) {
            const int fi = (((wn * 4 + nt) * 8 + ks) << 6) + lane * 2;
            B1c[nt * 8 + ks] = *(const uint2*)(W1f  + fi);
            B3c[nt * 8 + ks] = *(const uint2*)(Wrrf + fi);
        }

    const int ntiles = (E + TILE_E - 1) / TILE_E;

    for (int tile = blockIdx.x; tile < ntiles; tile += gridDim.x) {
        const int base = tile * TILE_E;
        const int n_e  = min(TILE_E, E - base);

        // ---- stage 0: X = softmax(m_i*m_j) closed form -> A0 (tf32 bits) ----
        {
            const int e  = tid >> 2;          // edge in tile
            const int qq = tid & 3;           // 16-feature quadrant
            const int eg = base + (e < n_e ? e : n_e - 1);
            const int mrowi = omI[eg];
            const int jj    = atI[eg];
            if (qq == 0) { sObs[e] = obsI[eg]; sJ[e] = jj; }
            const float* mrow = km + (size_t)mrowi * 64;
            float mv[16];
            float s = 0.f;
            #pragma unroll
            for (int t = 0; t < 4; t++) {
                float4 v = *(const float4*)(mrow + qq * 16 + t * 4);
                mv[t*4+0]=v.x; mv[t*4+1]=v.y; mv[t*4+2]=v.z; mv[t*4+3]=v.w;
                s += v.x + v.y + v.z + v.w;
            }
            s += __shfl_xor_sync(0xffffffffu, s, 1);
            s += __shfl_xor_sync(0xffffffffu, s, 2);
            const float kn = s - mrow[jj];
            const float EU = 2.71828182845904523536f;
            const float alpha = 1.f / (kn * EU + (64.f - kn));
            const uint32_t ua = f2tf(alpha);
            const uint32_t ub = f2tf(EU * alpha);
            uint32_t w[16];
            #pragma unroll
            for (int t = 0; t < 16; t++) {
                const int f = qq * 16 + t;
                w[t] = (mv[t] != 0.f && f != jj) ? ub : ua;
            }
            uint4* dst = (uint4*)(A0 + e * STR0 + qq * 16);
            dst[0] = make_uint4(w[0],  w[1],  w[2],  w[3]);
            dst[1] = make_uint4(w[4],  w[5],  w[6],  w[7]);
            dst[2] = make_uint4(w[8],  w[9],  w[10], w[11]);
            dst[3] = make_uint4(w[12], w[13], w[14], w[15]);
        }
        __syncthreads();

        // ---- stage 1: H = gelu(X @ W1 + b1) -> A1   (K=64, N=128, B cached) ----
        {
            float acc[2][4][4];
            #pragma unroll
            for (int m = 0; m < 2; m++)
                #pragma unroll
                for (int nt = 0; nt < 4; nt++)
                    { acc[m][nt][0]=0.f; acc[m][nt][1]=0.f; acc[m][nt][2]=0.f; acc[m][nt][3]=0.f; }
            #pragma unroll
            for (int m = 0; m < 2; m++) {
                const uint32_t* a0p = A0 + (wm * 32 + m * 16 + r) * STR0 + q;
                const uint32_t* a1p = a0p + 8 * STR0;
                #pragma unroll
                for (int ks = 0; ks < 8; ks++) {
                    const uint32_t a0 = a0p[ks*8], a2 = a0p[ks*8+4];
                    const uint32_t a1 = a1p[ks*8], a3 = a1p[ks*8+4];
                    #pragma unroll
                    for (int nt = 0; nt < 4; nt++)
                        mma8(acc[m][nt], a0, a1, a2, a3, B1c[nt*8+ks].x, B1c[nt*8+ks].y);
                }
            }
            #pragma unroll
            for (int m = 0; m < 2; m++) {
                const int e0 = wm * 32 + m * 16 + r;
                #pragma unroll
                for (int nt = 0; nt < 4; nt++) {
                    const int n0 = (wn * 4 + nt) * 8 + 2 * q;
                    const float2 bb = *(const float2*)(sb1 + n0);
                    uint2 lo, hi;
                    lo.x = f2tf(gelu_f(acc[m][nt][0] + bb.x));
                    lo.y = f2tf(gelu_f(acc[m][nt][1] + bb.y));
                    hi.x = f2tf(gelu_f(acc[m][nt][2] + bb.x));
                    hi.y = f2tf(gelu_f(acc[m][nt][3] + bb.y));
                    *(uint2*)(A1 + e0 * STR1 + n0)       = lo;
                    *(uint2*)(A1 + (e0 + 8) * STR1 + n0) = hi;
                }
            }
        }
        __syncthreads();

        // ---- stage 2: T = fea_corr[j] * gelu(H @ W2 + b2) -> A0   (K=128, N=64) ----
        {
            float acc[2][2][4];
            #pragma unroll
            for (int m = 0; m < 2; m++)
                #pragma unroll
                for (int nt = 0; nt < 2; nt++)
                    { acc[m][nt][0]=0.f; acc[m][nt][1]=0.f; acc[m][nt][2]=0.f; acc[m][nt][3]=0.f; }
            #pragma unroll
            for (int m = 0; m < 2; m++) {
                const uint32_t* a0p = A1 + (wm * 32 + m * 16 + r) * STR1 + q;
                const uint32_t* a1p = a0p + 8 * STR1;
                #pragma unroll
                for (int ks = 0; ks < 16; ks++) {
                    const uint32_t a0 = a0p[ks*8], a2 = a0p[ks*8+4];
                    const uint32_t a1 = a1p[ks*8], a3 = a1p[ks*8+4];
                    #pragma unroll
                    for (int nt = 0; nt < 2; nt++) {
                        const uint2 b = *(const uint2*)(W2f + (((wn*2+nt)*16+ks)<<6) + lane*2);
                        mma8(acc[m][nt], a0, a1, a2, a3, b.x, b.y);
                    }
                }
            }
            #pragma unroll
            for (int m = 0; m < 2; m++) {
                const int e0 = wm * 32 + m * 16 + r, e1 = e0 + 8;
                const int j0 = sJ[e0], j1 = sJ[e1];
                #pragma unroll
                for (int nt = 0; nt < 2; nt++) {
                    const int n0 = (wn * 2 + nt) * 8 + 2 * q;
                    const float2 bb = *(const float2*)(sb2 + n0);
                    const float2 f0 = __ldg((const float2*)(fcorr + (size_t)j0 * 64 + n0));
                    const float2 f1 = __ldg((const float2*)(fcorr + (size_t)j1 * 64 + n0));
                    uint2 lo, hi;
                    lo.x = f2tf(f0.x * gelu_f(acc[m][nt][0] + bb.x));
                    lo.y = f2tf(f0.y * gelu_f(acc[m][nt][1] + bb.y));
                    hi.x = f2tf(f1.x * gelu_f(acc[m][nt][2] + bb.x));
                    hi.y = f2tf(f1.y * gelu_f(acc[m][nt][3] + bb.y));
                    *(uint2*)(A0 + e0 * STR0 + n0) = lo;
                    *(uint2*)(A0 + e1 * STR0 + n0) = hi;
                }
            }
        }
        __syncthreads();

        // ---- stage 3: U = obs_h * gelu(T @ Wrr + brr) -> A1   (K=64, N=128, B cached) ----
        {
            float acc[2][4][4];
            #pragma unroll
            for (int m = 0; m < 2; m++)
                #pragma unroll
                for (int nt = 0; nt < 4; nt++)
                    { acc[m][nt][0]=0.f; acc[m][nt][1]=0.f; acc[m][nt][2]=0.f; acc[m][nt][3]=0.f; }
            #pragma unroll
            for (int m = 0; m < 2; m++) {
                const uint32_t* a0p = A0 + (wm * 32 + m * 16 + r) * STR0 + q;
                const uint32_t* a1p = a0p + 8 * STR0;
                #pragma unroll
                for (int ks = 0; ks < 8; ks++) {
                    const uint32_t a0 = a0p[ks*8], a2 = a0p[ks*8+4];
                    const uint32_t a1 = a1p[ks*8], a3 = a1p[ks*8+4];
                    #pragma unroll
                    for (int nt = 0; nt < 4; nt++)
                        mma8(acc[m][nt], a0, a1, a2, a3, B3c[nt*8+ks].x, B3c[nt*8+ks].y);
                }
            }
            #pragma unroll
            for (int m = 0; m < 2; m++) {
                const int e0 = wm * 32 + m * 16 + r, e1 = e0 + 8;
                const size_t o0 = (size_t)sObs[e0] * 128;
                const size_t o1 = (size_t)sObs[e1] * 128;
                #pragma unroll
                for (int nt = 0; nt < 4; nt++) {
                    const int n0 = (wn * 4 + nt) * 8 + 2 * q;
                    const float2 bb = *(const float2*)(sbrr + n0);
                    const float2 v0 = __ldg((const float2*)(obsE + o0 + n0));
                    const float2 v1 = __ldg((const float2*)(obsE + o1 + n0));
                    uint2 lo, hi;
                    lo.x = f2tf(v0.x * gelu_f(acc[m][nt][0] + bb.x));
                    lo.y = f2tf(v0.y * gelu_f(acc[m][nt][1] + bb.y));
                    hi.x = f2tf(v1.x * gelu_f(acc[m][nt][2] + bb.x));
                    hi.y = f2tf(v1.y * gelu_f(acc[m][nt][3] + bb.y));
                    *(uint2*)(A1 + e0 * STR1 + n0) = lo;
                    *(uint2*)(A1 + e1 * STR1 + n0) = hi;
                }
            }
        }
        __syncthreads();

        // ---- stage 4: out = gelu(U @ Wrc + brc) -> global   (K=128, N=128) ----
        {
            float acc[2][4][4];
            #pragma unroll
            for (int m = 0; m < 2; m++)
                #pragma unroll
                for (int nt = 0; nt < 4; nt++)
                    { acc[m][nt][0]=0.f; acc[m][nt][1]=0.f; acc[m][nt][2]=0.f; acc[m][nt][3]=0.f; }
            #pragma unroll
            for (int m = 0; m < 2; m++) {
                const uint32_t* a0p = A1 + (wm * 32 + m * 16 + r) * STR1 + q;
                const uint32_t* a1p = a0p + 8 * STR1;
                #pragma unroll
                for (int ks = 0; ks < 16; ks++) {
                    const uint32_t a0 = a0p[ks*8], a2 = a0p[ks*8+4];
                    const uint32_t a1 = a1p[ks*8], a3 = a1p[ks*8+4];
                    #pragma unroll
                    for (int nt = 0; nt < 4; nt++) {
                        const uint2 b = *(const uint2*)(Wrcf + (((wn*4+nt)*16+ks)<<6) + lane*2);
                        mma8(acc[m][nt], a0, a1, a2, a3, b.x, b.y);
                    }
                }
            }
            #pragma unroll
            for (int m = 0; m < 2; m++) {
                const int e0 = wm * 32 + m * 16 + r, e1 = e0 + 8;
                float* o0 = out + (size_t)(base + e0) * 128;
                float* o1 = out + (size_t)(base + e1) * 128;
                #pragma unroll
                for (int nt = 0; nt < 4; nt++) {
                    const int n0 = (wn * 4 + nt) * 8 + 2 * q;
                    const float2 bb = *(const float2*)(sbrc + n0);
                    if (e0 < n_e) {
                        float2 v;
                        v.x = gelu_f(acc[m][nt][0] + bb.x);
                        v.y = gelu_f(acc[m][nt][1] + bb.y);
                        *(float2*)(o0 + n0) = v;
                    }
                    if (e1 < n_e) {
                        float2 v;
                        v.x = gelu_f(acc[m][nt][2] + bb.x);
                        v.y = gelu_f(acc[m][nt][3] + bb.y);
                        *(float2*)(o1 + n0) = v;
                    }
                }
            }
        }
        __syncthreads();   // protects sObs/sJ/A0 before next tile's stage 0
    }
}

extern "C" void kernel_launch(void* const* d_in, const int* in_sizes, int n_in,
                              void* d_out, int out_size) {
    const float* known_mask   = (const float*)d_in[0];
    const int*   obs_idx      = (const int*)  d_in[1];
    const int*   obs_mask_idx = (const int*)  d_in[2];
    const int*   attr_idx     = (const int*)  d_in[3];
    const float* obs_embs     = (const float*)d_in[4];
    const float* fea_corr     = (const float*)d_in[5];
    const float* W1  = (const float*)d_in[6];
    const float* b1  = (const float*)d_in[7];
    const float* W2  = (const float*)d_in[8];
    const float* b2  = (const float*)d_in[9];
    const float* Wrr = (const float*)d_in[10];
    const float* brr = (const float*)d_in[11];
    const float* Wrc = (const float*)d_in[12];
    const float* brc = (const float*)d_in[13];
    const int E = in_sizes[1];

    int sms = 148;
    cudaDeviceGetAttribute(&sms, cudaDevAttrMultiProcessorCount, 0);
    cudaFuncSetAttribute(attr_rel_mma,
                         cudaFuncAttributeMaxDynamicSharedMemorySize, SMEM_BYTES);

    attr_rel_mma<<<sms, NTHREADS, SMEM_BYTES>>>(
        known_mask, obs_idx, obs_mask_idx, attr_idx, obs_embs, fea_corr,
        W1, b1, W2, b2, Wrr, brr, Wrc, brc,
        (float*)d_out, E);
}

// round 9
// speedup vs baseline: 2.4531x; 1.0224x over previous
#include <cuda_runtime.h>
#include <math.h>
#include <stdint.h>

#define NTHREADS 256
#define TILE_E   32          // edges per group-tile

// ---------------- smem layout (bytes) ----------------
#define OFF_W1F   0          // W1  frags [64x128]  32768
#define OFF_W2F   32768      // W2  frags [128x64]  32768
#define OFF_WRRF  65536      // Wrr frags [64x128]  32768
#define OFF_WRCF  98304      // Wrc frags [128x128] 65536
#define OFF_A0    163840     // 2 groups x (32 x 68 floats)  = 2 x 8704
#define OFF_A1    181248     // 2 groups x (32 x 132 floats) = 2 x 16896
#define OFF_B1    215040     // 128 f
#define OFF_B2    215552     // 64 f
#define OFF_BRR   215808     // 128 f
#define OFF_BRC   216320     // 128 f
#define OFF_OBS   216832     // 2 x 32 int
#define OFF_J     217088     // 2 x 32 int
#define SMEM_BYTES 217600

#define STR0 68    // word stride, A0: bank=(4r+q)%32 conflict-free
#define STR1 132   // word stride, A1

__device__ __forceinline__ float gelu_f(float x) {
    return 0.5f * x * (1.0f + erff(x * 0.70710678118654752440f));
}

__device__ __forceinline__ uint32_t f2tf(float x) {
    uint32_t r;
    asm("cvt.rna.tf32.f32 %0, %1;" : "=r"(r) : "f"(x));
    return r;
}

__device__ __forceinline__ void mma8(float d[4], uint32_t a0, uint32_t a1,
                                     uint32_t a2, uint32_t a3,
                                     uint32_t b0, uint32_t b1) {
    asm volatile(
        "mma.sync.aligned.m16n8k8.row.col.f32.tf32.tf32.f32 "
        "{%0,%1,%2,%3}, {%4,%5,%6,%7}, {%8,%9}, {%0,%1,%2,%3};"
        : "+f"(d[0]), "+f"(d[1]), "+f"(d[2]), "+f"(d[3])
        : "r"(a0), "r"(a1), "r"(a2), "r"(a3), "r"(b0), "r"(b1));
}

#define GBAR() asm volatile("bar.sync %0, 128;" :: "r"(grp + 1) : "memory")

// W global [K,N] row-major -> tf32 B-fragment order
__device__ __forceinline__ void prep_frag(const float* __restrict__ W, int K, int N,
                                          uint32_t* __restrict__ dst, int tid) {
    const int K8 = K >> 3;
    for (int j = tid; j < K * N; j += NTHREADS) {
        const int reg  = j & 1;
        const int lane = (j >> 1) & 31;
        const int fk   = j >> 6;
        const int ks   = fk % K8;
        const int nt   = fk / K8;
        const int k = ks * 8 + (lane & 3) + reg * 4;
        const int n = nt * 8 + (lane >> 2);
        dst[j] = f2tf(W[k * N + n]);
    }
}

__global__ void __launch_bounds__(NTHREADS, 1)
attr_rel_mma(const float* __restrict__ km,  const int* __restrict__ obsI,
             const int* __restrict__ omI,   const int* __restrict__ atI,
             const float* __restrict__ obsE, const float* __restrict__ fcorr,
             const float* __restrict__ W1,  const float* __restrict__ b1,
             const float* __restrict__ W2,  const float* __restrict__ b2,
             const float* __restrict__ Wrr, const float* __restrict__ brr,
             const float* __restrict__ Wrc, const float* __restrict__ brc,
             float* __restrict__ out, int E)
{
    extern __shared__ char smem[];
    uint32_t* W1f  = (uint32_t*)(smem + OFF_W1F);
    uint32_t* W2f  = (uint32_t*)(smem + OFF_W2F);
    uint32_t* Wrrf = (uint32_t*)(smem + OFF_WRRF);
    uint32_t* Wrcf = (uint32_t*)(smem + OFF_WRCF);
    float* sb1  = (float*)(smem + OFF_B1);
    float* sb2  = (float*)(smem + OFF_B2);
    float* sbrr = (float*)(smem + OFF_BRR);
    float* sbrc = (float*)(smem + OFF_BRC);

    const int tid  = threadIdx.x;
    const int warp = tid >> 5;
    const int lane = tid & 31;
    const int grp  = warp >> 2;          // work-group 0/1
    const int wl   = warp & 3;           // N-group within work-group
    const int tg   = tid & 127;          // thread id within group
    const int r    = lane >> 2;
    const int q    = lane & 3;

    // per-group activation buffers + index arrays
    uint32_t* A0 = (uint32_t*)(smem + OFF_A0) + grp * (TILE_E * STR0);
    uint32_t* A1 = (uint32_t*)(smem + OFF_A1) + grp * (TILE_E * STR1);
    int* sObs = (int*)(smem + OFF_OBS) + grp * TILE_E;
    int* sJ   = (int*)(smem + OFF_J)   + grp * TILE_E;

    // ---- one-time weight prep (fragment order, tf32-rounded) ----
    prep_frag(W1,   64, 128, W1f,  tid);
    prep_frag(W2,  128,  64, W2f,  tid);
    prep_frag(Wrr,  64, 128, Wrrf, tid);
    prep_frag(Wrc, 128, 128, Wrcf, tid);
    for (int i = tid; i < 128; i += NTHREADS) sb1[i]  = b1[i];
    for (int i = tid; i < 64;  i += NTHREADS) sb2[i]  = b2[i];
    for (int i = tid; i < 128; i += NTHREADS) sbrr[i] = brr[i];
    for (int i = tid; i < 128; i += NTHREADS) sbrc[i] = brc[i];
    __syncthreads();

    const int ntiles = (E + TILE_E - 1) / TILE_E;

    for (int tile = blockIdx.x * 2 + grp; tile < ntiles; tile += gridDim.x * 2) {
        const int base = tile * TILE_E;
        const int n_e  = min(TILE_E, E - base);

        // ---- stage 0: X = softmax(m_i*m_j) closed form -> A0 (tf32 bits) ----
        {
            const int e  = tg >> 2;           // edge in tile (0..31)
            const int qq = tg & 3;            // 16-feature quadrant
            const int eg = base + (e < n_e ? e : n_e - 1);
            const int mrowi = omI[eg];
            const int jj    = atI[eg];
            if (qq == 0) { sObs[e] = obsI[eg]; sJ[e] = jj; }
            const float* mrow = km + (size_t)mrowi * 64;
            float mv[16];
            float s = 0.f;
            #pragma unroll
            for (int t = 0; t < 4; t++) {
                float4 v = *(const float4*)(mrow + qq * 16 + t * 4);
                mv[t*4+0]=v.x; mv[t*4+1]=v.y; mv[t*4+2]=v.z; mv[t*4+3]=v.w;
                s += v.x + v.y + v.z + v.w;
            }
            s += __shfl_xor_sync(0xffffffffu, s, 1);
            s += __shfl_xor_sync(0xffffffffu, s, 2);
            const float kn = s - mrow[jj];
            const float EU = 2.71828182845904523536f;
            const float alpha = 1.f / (kn * EU + (64.f - kn));
            const uint32_t ua = f2tf(alpha);
            const uint32_t ub = f2tf(EU * alpha);
            uint32_t w[16];
            #pragma unroll
            for (int t = 0; t < 16; t++) {
                const int f = qq * 16 + t;
                w[t] = (mv[t] != 0.f && f != jj) ? ub : ua;
            }
            uint4* dst = (uint4*)(A0 + e * STR0 + qq * 16);
            dst[0] = make_uint4(w[0],  w[1],  w[2],  w[3]);
            dst[1] = make_uint4(w[4],  w[5],  w[6],  w[7]);
            dst[2] = make_uint4(w[8],  w[9],  w[10], w[11]);
            dst[3] = make_uint4(w[12], w[13], w[14], w[15]);
        }
        GBAR();

        // ---- stage 1: H = gelu(X @ W1 + b1) -> A1   (K=64, N=128) ----
        {
            float acc[2][4][4];
            #pragma unroll
            for (int m = 0; m < 2; m++)
                #pragma unroll
                for (int nt = 0; nt < 4; nt++)
                    { acc[m][nt][0]=0.f; acc[m][nt][1]=0.f; acc[m][nt][2]=0.f; acc[m][nt][3]=0.f; }
            #pragma unroll
            for (int m = 0; m < 2; m++) {
                const uint32_t* a0p = A0 + (m * 16 + r) * STR0 + q;
                const uint32_t* a1p = a0p + 8 * STR0;
                #pragma unroll
                for (int ks = 0; ks < 8; ks++) {
                    const uint32_t a0 = a0p[ks*8], a2 = a0p[ks*8+4];
                    const uint32_t a1 = a1p[ks*8], a3 = a1p[ks*8+4];
                    #pragma unroll
                    for (int nt = 0; nt < 4; nt++) {
                        const uint2 b = *(const uint2*)(W1f + (((wl*4+nt)*8+ks)<<6) + lane*2);
                        mma8(acc[m][nt], a0, a1, a2, a3, b.x, b.y);
                    }
                }
            }
            #pragma unroll
            for (int m = 0; m < 2; m++) {
                const int e0 = m * 16 + r;
                #pragma unroll
                for (int nt = 0; nt < 4; nt++) {
                    const int n0 = (wl * 4 + nt) * 8 + 2 * q;
                    const float2 bb = *(const float2*)(sb1 + n0);
                    uint2 lo, hi;
                    lo.x = f2tf(gelu_f(acc[m][nt][0] + bb.x));
                    lo.y = f2tf(gelu_f(acc[m][nt][1] + bb.y));
                    hi.x = f2tf(gelu_f(acc[m][nt][2] + bb.x));
                    hi.y = f2tf(gelu_f(acc[m][nt][3] + bb.y));
                    *(uint2*)(A1 + e0 * STR1 + n0)       = lo;
                    *(uint2*)(A1 + (e0 + 8) * STR1 + n0) = hi;
                }
            }
        }
        GBAR();

        // ---- stage 2: T = fea_corr[j] * gelu(H @ W2 + b2) -> A0   (K=128, N=64) ----
        {
            float acc[2][2][4];
            #pragma unroll
            for (int m = 0; m < 2; m++)
                #pragma unroll
                for (int nt = 0; nt < 2; nt++)
                    { acc[m][nt][0]=0.f; acc[m][nt][1]=0.f; acc[m][nt][2]=0.f; acc[m][nt][3]=0.f; }
            #pragma unroll
            for (int m = 0; m < 2; m++) {
                const uint32_t* a0p = A1 + (m * 16 + r) * STR1 + q;
                const uint32_t* a1p = a0p + 8 * STR1;
                #pragma unroll
                for (int ks = 0; ks < 16; ks++) {
                    const uint32_t a0 = a0p[ks*8], a2 = a0p[ks*8+4];
                    const uint32_t a1 = a1p[ks*8], a3 = a1p[ks*8+4];
                    #pragma unroll
                    for (int nt = 0; nt < 2; nt++) {
                        const uint2 b = *(const uint2*)(W2f + (((wl*2+nt)*16+ks)<<6) + lane*2);
                        mma8(acc[m][nt], a0, a1, a2, a3, b.x, b.y);
                    }
                }
            }
            #pragma unroll
            for (int m = 0; m < 2; m++) {
                const int e0 = m * 16 + r, e1 = e0 + 8;
                const int j0 = sJ[e0], j1 = sJ[e1];
                #pragma unroll
                for (int nt = 0; nt < 2; nt++) {
                    const int n0 = (wl * 2 + nt) * 8 + 2 * q;
                    const float2 bb = *(const float2*)(sb2 + n0);
                    const float2 f0 = __ldg((const float2*)(fcorr + (size_t)j0 * 64 + n0));
                    const float2 f1 = __ldg((const float2*)(fcorr + (size_t)j1 * 64 + n0));
                    uint2 lo, hi;
                    lo.x = f2tf(f0.x * gelu_f(acc[m][nt][0] + bb.x));
                    lo.y = f2tf(f0.y * gelu_f(acc[m][nt][1] + bb.y));
                    hi.x = f2tf(f1.x * gelu_f(acc[m][nt][2] + bb.x));
                    hi.y = f2tf(f1.y * gelu_f(acc[m][nt][3] + bb.y));
                    *(uint2*)(A0 + e0 * STR0 + n0) = lo;
                    *(uint2*)(A0 + e1 * STR0 + n0) = hi;
                }
            }
        }
        GBAR();

        // ---- stage 3: U = obs_h * gelu(T @ Wrr + brr) -> A1   (K=64, N=128) ----
        {
            float acc[2][4][4];
            #pragma unroll
            for (int m = 0; m < 2; m++)
                #pragma unroll
                for (int nt = 0; nt < 4; nt++)
                    { acc[m][nt][0]=0.f; acc[m][nt][1]=0.f; acc[m][nt][2]=0.f; acc[m][nt][3]=0.f; }
            #pragma unroll
            for (int m = 0; m < 2; m++) {
                const uint32_t* a0p = A0 + (m * 16 + r) * STR0 + q;
                const uint32_t* a1p = a0p + 8 * STR0;
                #pragma unroll
                for (int ks = 0; ks < 8; ks++) {
                    const uint32_t a0 = a0p[ks*8], a2 = a0p[ks*8+4];
                    const uint32_t a1 = a1p[ks*8], a3 = a1p[ks*8+4];
                    #pragma unroll
                    for (int nt = 0; nt < 4; nt++) {
                        const uint2 b = *(const uint2*)(Wrrf + (((wl*4+nt)*8+ks)<<6) + lane*2);
                        mma8(acc[m][nt], a0, a1, a2, a3, b.x, b.y);
                    }
                }
            }
            #pragma unroll
            for (int m = 0; m < 2; m++) {
                const int e0 = m * 16 + r, e1 = e0 + 8;
                const size_t o0 = (size_t)sObs[e0] * 128;
                const size_t o1 = (size_t)sObs[e1] * 128;
                #pragma unroll
                for (int nt = 0; nt < 4; nt++) {
                    const int n0 = (wl * 4 + nt) * 8 + 2 * q;
                    const float2 bb = *(const float2*)(sbrr + n0);
                    const float2 v0 = __ldg((const float2*)(obsE + o0 + n0));
                    const float2 v1 = __ldg((const float2*)(obsE + o1 + n0));
                    uint2 lo, hi;
                    lo.x = f2tf(v0.x * gelu_f(acc[m][nt][0] + bb.x));
                    lo.y = f2tf(v0.y * gelu_f(acc[m][nt][1] + bb.y));
                    hi.x = f2tf(v1.x * gelu_f(acc[m][nt][2] + bb.x));
                    hi.y = f2tf(v1.y * gelu_f(acc[m][nt][3] + bb.y));
                    *(uint2*)(A1 + e0 * STR1 + n0) = lo;
                    *(uint2*)(A1 + e1 * STR1 + n0) = hi;
                }
            }
        }
        GBAR();

        // ---- stage 4: out = gelu(U @ Wrc + brc) -> global   (K=128, N=128) ----
        {
            float acc[2][4][4];
            #pragma unroll
            for (int m = 0; m < 2; m++)
                #pragma unroll
                for (int nt = 0; nt < 4; nt++)
                    { acc[m][nt][0]=0.f; acc[m][nt][1]=0.f; acc[m][nt][2]=0.f; acc[m][nt][3]=0.f; }
            #pragma unroll
            for (int m = 0; m < 2; m++) {
                const uint32_t* a0p = A1 + (m * 16 + r) * STR1 + q;
                const uint32_t* a1p = a0p + 8 * STR1;
                #pragma unroll
                for (int ks = 0; ks < 16; ks++) {
                    const uint32_t a0 = a0p[ks*8], a2 = a0p[ks*8+4];
                    const uint32_t a1 = a1p[ks*8], a3 = a1p[ks*8+4];
                    #pragma unroll
                    for (int nt = 0; nt < 4; nt++) {
                        const uint2 b = *(const uint2*)(Wrcf + (((wl*4+nt)*16+ks)<<6) + lane*2);
                        mma8(acc[m][nt], a0, a1, a2, a3, b.x, b.y);
                    }
                }
            }
            #pragma unroll
            for (int m = 0; m < 2; m++) {
                const int e0 = m * 16 + r, e1 = e0 + 8;
                float* o0 = out + (size_t)(base + e0) * 128;
                float* o1 = out + (size_t)(base + e1) * 128;
                #pragma unroll
                for (int nt = 0; nt < 4; nt++) {
                    const int n0 = (wl * 4 + nt) * 8 + 2 * q;
                    const float2 bb = *(const float2*)(sbrc + n0);
                    if (e0 < n_e) {
                        float2 v;
                        v.x = gelu_f(acc[m][nt][0] + bb.x);
                        v.y = gelu_f(acc[m][nt][1] + bb.y);
                        *(float2*)(o0 + n0) = v;
                    }
                    if (e1 < n_e) {
                        float2 v;
                        v.x = gelu_f(acc[m][nt][2] + bb.x);
                        v.y = gelu_f(acc[m][nt][3] + bb.y);
                        *(float2*)(o1 + n0) = v;
                    }
                }
            }
        }
        GBAR();   // protects A0/sObs/sJ before next tile's stage 0
    }
}

extern "C" void kernel_launch(void* const* d_in, const int* in_sizes, int n_in,
                              void* d_out, int out_size) {
    const float* known_mask   = (const float*)d_in[0];
    const int*   obs_idx      = (const int*)  d_in[1];
    const int*   obs_mask_idx = (const int*)  d_in[2];
    const int*   attr_idx     = (const int*)  d_in[3];
    const float* obs_embs     = (const float*)d_in[4];
    const float* fea_corr     = (const float*)d_in[5];
    const float* W1  = (const float*)d_in[6];
    const float* b1  = (const float*)d_in[7];
    const float* W2  = (const float*)d_in[8];
    const float* b2  = (const float*)d_in[9];
    const float* Wrr = (const float*)d_in[10];
    const float* brr = (const float*)d_in[11];
    const float* Wrc = (const float*)d_in[12];
    const float* brc = (const float*)d_in[13];
    const int E = in_sizes[1];

    int sms = 148;
    cudaDeviceGetAttribute(&sms, cudaDevAttrMultiProcessorCount, 0);
    cudaFuncSetAttribute(attr_rel_mma,
                         cudaFuncAttributeMaxDynamicSharedMemorySize, SMEM_BYTES);

    attr_rel_mma<<<sms, NTHREADS, SMEM_BYTES>>>(
        known_mask, obs_idx, obs_mask_idx, attr_idx, obs_embs, fea_corr,
        W1, b1, W2, b2, Wrr, brr, Wrc, brc,
        (float*)d_out, E);
}

// round 10
// speedup vs baseline: 2.5615x; 1.0442x over previous
#include <cuda_runtime.h>
#include <math.h>
#include <stdint.h>

#define NTHREADS 256
#define TILE_E   32          // edges per group-tile

// ---------------- smem layout (bytes) ----------------
#define OFF_W1F   0          // W1  frags [64x128]  32768
#define OFF_W2F   32768      // W2  frags [128x64]  32768
#define OFF_WRRF  65536      // Wrr frags [64x128]  32768
#define OFF_WRCF  98304      // Wrc frags [128x128] 65536
#define OFF_A0    163840     // 2 groups x (32 x 68 floats)  = 2 x 8704
#define OFF_A1    181248     // 2 groups x (32 x 132 floats) = 2 x 16896
#define OFF_B1    215040     // 128 f
#define OFF_B2    215552     // 64 f
#define OFF_BRR   215808     // 128 f
#define OFF_BRC   216320     // 128 f
#define OFF_OBS   216832     // 2 x 32 int
#define OFF_J     217088     // 2 x 32 int
#define SMEM_BYTES 217600

#define STR0 68    // word stride, A0: rows 4 banks apart -> LDSM conflict-free
#define STR1 132   // word stride, A1

// Fast exact-GELU: erf via Abramowitz-Stegun 7.1.26 (|eps| <= 1.5e-7).
// gelu(x) = 0.5*x + 0.5*|x|*erf(|x|/sqrt2)   (sign folded into |x| term)
__device__ __forceinline__ float gelu_f(float x) {
    const float ax = fabsf(x);
    const float z  = ax * 0.70710678118654752f;
    const float den = fmaf(0.3275911f, z, 1.0f);
    float t;
    asm("rcp.approx.f32 %0, %1;" : "=f"(t) : "f"(den));
    float p = fmaf(t, 1.061405429f, -1.453152027f);
    p = fmaf(t, p, 1.421413741f);
    p = fmaf(t, p, -0.284496736f);
    p = fmaf(t, p, 0.254829592f);
    p = p * t;
    const float e = __expf(-z * z);
    const float erfz = fmaf(-e, p, 1.0f);          // erf(|x|/sqrt2)
    return fmaf(0.5f * ax, erfz, 0.5f * x);
}

__device__ __forceinline__ uint32_t f2tf(float x) {
    uint32_t r;
    asm("cvt.rna.tf32.f32 %0, %1;" : "=r"(r) : "f"(x));
    return r;
}

__device__ __forceinline__ void mma8(float d[4], uint32_t a0, uint32_t a1,
                                     uint32_t a2, uint32_t a3,
                                     uint32_t b0, uint32_t b1) {
    asm volatile(
        "mma.sync.aligned.m16n8k8.row.col.f32.tf32.tf32.f32 "
        "{%0,%1,%2,%3}, {%4,%5,%6,%7}, {%8,%9}, {%0,%1,%2,%3};"
        : "+f"(d[0]), "+f"(d[1]), "+f"(d[2]), "+f"(d[3])
        : "r"(a0), "r"(a1), "r"(a2), "r"(a3), "r"(b0), "r"(b1));
}

// A-fragment (m16k8 tf32) in one ldmatrix.x4 (b16 view, b32 semantics)
__device__ __forceinline__ void ldsm4(uint32_t& a0, uint32_t& a1,
                                      uint32_t& a2, uint32_t& a3, uint32_t addr) {
    asm volatile("ldmatrix.sync.aligned.m8n8.x4.shared.b16 {%0,%1,%2,%3}, [%4];"
                 : "=r"(a0), "=r"(a1), "=r"(a2), "=r"(a3) : "r"(addr));
}

#define GBAR() asm volatile("bar.sync %0, 128;" :: "r"(grp + 1) : "memory")

// W global [K,N] row-major -> tf32 B-fragment order
__device__ __forceinline__ void prep_frag(const float* __restrict__ W, int K, int N,
                                          uint32_t* __restrict__ dst, int tid) {
    const int K8 = K >> 3;
    for (int j = tid; j < K * N; j += NTHREADS) {
        const int reg  = j & 1;
        const int lane = (j >> 1) & 31;
        const int fk   = j >> 6;
        const int ks   = fk % K8;
        const int nt   = fk / K8;
        const int k = ks * 8 + (lane & 3) + reg * 4;
        const int n = nt * 8 + (lane >> 2);
        dst[j] = f2tf(W[k * N + n]);
    }
}

__global__ void __launch_bounds__(NTHREADS, 1)
attr_rel_mma(const float* __restrict__ km,  const int* __restrict__ obsI,
             const int* __restrict__ omI,   const int* __restrict__ atI,
             const float* __restrict__ obsE, const float* __restrict__ fcorr,
             const float* __restrict__ W1,  const float* __restrict__ b1,
             const float* __restrict__ W2,  const float* __restrict__ b2,
             const float* __restrict__ Wrr, const float* __restrict__ brr,
             const float* __restrict__ Wrc, const float* __restrict__ brc,
             float* __restrict__ out, int E)
{
    extern __shared__ char smem[];
    uint32_t* W1f  = (uint32_t*)(smem + OFF_W1F);
    uint32_t* W2f  = (uint32_t*)(smem + OFF_W2F);
    uint32_t* Wrrf = (uint32_t*)(smem + OFF_WRRF);
    uint32_t* Wrcf = (uint32_t*)(smem + OFF_WRCF);
    float* sb1  = (float*)(smem + OFF_B1);
    float* sb2  = (float*)(smem + OFF_B2);
    float* sbrr = (float*)(smem + OFF_BRR);
    float* sbrc = (float*)(smem + OFF_BRC);

    const int tid  = threadIdx.x;
    const int warp = tid >> 5;
    const int lane = tid & 31;
    const int grp  = warp >> 2;          // work-group 0/1
    const int wl   = warp & 3;           // N-group within work-group
    const int tg   = tid & 127;          // thread id within group
    const int r    = lane >> 2;
    const int q    = lane & 3;

    // per-group activation buffers + index arrays
    uint32_t* A0 = (uint32_t*)(smem + OFF_A0) + grp * (TILE_E * STR0);
    uint32_t* A1 = (uint32_t*)(smem + OFF_A1) + grp * (TILE_E * STR1);
    int* sObs = (int*)(smem + OFF_OBS) + grp * TILE_E;
    int* sJ   = (int*)(smem + OFF_J)   + grp * TILE_E;

    const uint32_t A0u = (uint32_t)__cvta_generic_to_shared(A0);
    const uint32_t A1u = (uint32_t)__cvta_generic_to_shared(A1);
    // ldmatrix per-lane row/col offsets for the m16k8 A fragment
    const int rowoff = (lane & 7) + ((lane >> 3) & 1) * 8;
    const int coloff = (lane >> 4) << 2;

    // ---- one-time weight prep (fragment order, tf32-rounded) ----
    prep_frag(W1,   64, 128, W1f,  tid);
    prep_frag(W2,  128,  64, W2f,  tid);
    prep_frag(Wrr,  64, 128, Wrrf, tid);
    prep_frag(Wrc, 128, 128, Wrcf, tid);
    for (int i = tid; i < 128; i += NTHREADS) sb1[i]  = b1[i];
    for (int i = tid; i < 64;  i += NTHREADS) sb2[i]  = b2[i];
    for (int i = tid; i < 128; i += NTHREADS) sbrr[i] = brr[i];
    for (int i = tid; i < 128; i += NTHREADS) sbrc[i] = brc[i];
    __syncthreads();

    const int ntiles = (E + TILE_E - 1) / TILE_E;

    for (int tile = blockIdx.x * 2 + grp; tile < ntiles; tile += gridDim.x * 2) {
        const int base = tile * TILE_E;
        const int n_e  = min(TILE_E, E - base);

        // ---- stage 0: X = softmax(m_i*m_j) closed form -> A0 ----
        {
            const int e  = tg >> 2;           // edge in tile (0..31)
            const int qq = tg & 3;            // 16-feature quadrant
            const int eg = base + (e < n_e ? e : n_e - 1);
            const int mrowi = omI[eg];
            const int jj    = atI[eg];
            if (qq == 0) { sObs[e] = obsI[eg]; sJ[e] = jj; }
            const float* mrow = km + (size_t)mrowi * 64;
            float mv[16];
            float s = 0.f;
            #pragma unroll
            for (int t = 0; t < 4; t++) {
                float4 v = *(const float4*)(mrow + qq * 16 + t * 4);
                mv[t*4+0]=v.x; mv[t*4+1]=v.y; mv[t*4+2]=v.z; mv[t*4+3]=v.w;
                s += v.x + v.y + v.z + v.w;
            }
            s += __shfl_xor_sync(0xffffffffu, s, 1);
            s += __shfl_xor_sync(0xffffffffu, s, 2);
            const float kn = s - mrow[jj];
            const float EU = 2.71828182845904523536f;
            const float alpha = 1.f / (kn * EU + (64.f - kn));
            const uint32_t ua = f2tf(alpha);
            const uint32_t ub = f2tf(EU * alpha);
            uint32_t w[16];
            #pragma unroll
            for (int t = 0; t < 16; t++) {
                const int f = qq * 16 + t;
                w[t] = (mv[t] != 0.f && f != jj) ? ub : ua;
            }
            uint4* dst = (uint4*)(A0 + e * STR0 + qq * 16);
            dst[0] = make_uint4(w[0],  w[1],  w[2],  w[3]);
            dst[1] = make_uint4(w[4],  w[5],  w[6],  w[7]);
            dst[2] = make_uint4(w[8],  w[9],  w[10], w[11]);
            dst[3] = make_uint4(w[12], w[13], w[14], w[15]);
        }
        GBAR();

        // ---- stage 1: H = gelu(X @ W1 + b1) -> A1   (K=64, N=128) ----
        {
            float acc[2][4][4];
            #pragma unroll
            for (int m = 0; m < 2; m++)
                #pragma unroll
                for (int nt = 0; nt < 4; nt++)
                    { acc[m][nt][0]=0.f; acc[m][nt][1]=0.f; acc[m][nt][2]=0.f; acc[m][nt][3]=0.f; }
            #pragma unroll
            for (int m = 0; m < 2; m++) {
                const uint32_t ab = A0u + (((m * 16 + rowoff) * STR0 + coloff) << 2);
                #pragma unroll
                for (int ks = 0; ks < 8; ks++) {
                    uint32_t a0, a1, a2, a3;
                    ldsm4(a0, a1, a2, a3, ab + ks * 32);
                    #pragma unroll
                    for (int nt = 0; nt < 4; nt++) {
                        const uint2 b = *(const uint2*)(W1f + (((wl*4+nt)*8+ks)<<6) + lane*2);
                        mma8(acc[m][nt], a0, a1, a2, a3, b.x, b.y);
                    }
                }
            }
            #pragma unroll
            for (int m = 0; m < 2; m++) {
                const int e0 = m * 16 + r;
                #pragma unroll
                for (int nt = 0; nt < 4; nt++) {
                    const int n0 = (wl * 4 + nt) * 8 + 2 * q;
                    const float2 bb = *(const float2*)(sb1 + n0);
                    uint2 lo, hi;
                    lo.x = __float_as_uint(gelu_f(acc[m][nt][0] + bb.x));
                    lo.y = __float_as_uint(gelu_f(acc[m][nt][1] + bb.y));
                    hi.x = __float_as_uint(gelu_f(acc[m][nt][2] + bb.x));
                    hi.y = __float_as_uint(gelu_f(acc[m][nt][3] + bb.y));
                    *(uint2*)(A1 + e0 * STR1 + n0)       = lo;
                    *(uint2*)(A1 + (e0 + 8) * STR1 + n0) = hi;
                }
            }
        }
        GBAR();

        // ---- stage 2: T = fea_corr[j] * gelu(H @ W2 + b2) -> A0   (K=128, N=64) ----
        {
            float acc[2][2][4];
            #pragma unroll
            for (int m = 0; m < 2; m++)
                #pragma unroll
                for (int nt = 0; nt < 2; nt++)
                    { acc[m][nt][0]=0.f; acc[m][nt][1]=0.f; acc[m][nt][2]=0.f; acc[m][nt][3]=0.f; }
            #pragma unroll
            for (int m = 0; m < 2; m++) {
                const uint32_t ab = A1u + (((m * 16 + rowoff) * STR1 + coloff) << 2);
                #pragma unroll
                for (int ks = 0; ks < 16; ks++) {
                    uint32_t a0, a1, a2, a3;
                    ldsm4(a0, a1, a2, a3, ab + ks * 32);
                    #pragma unroll
                    for (int nt = 0; nt < 2; nt++) {
                        const uint2 b = *(const uint2*)(W2f + (((wl*2+nt)*16+ks)<<6) + lane*2);
                        mma8(acc[m][nt], a0, a1, a2, a3, b.x, b.y);
                    }
                }
            }
            #pragma unroll
            for (int m = 0; m < 2; m++) {
                const int e0 = m * 16 + r, e1 = e0 + 8;
                const int j0 = sJ[e0], j1 = sJ[e1];
                #pragma unroll
                for (int nt = 0; nt < 2; nt++) {
                    const int n0 = (wl * 2 + nt) * 8 + 2 * q;
                    const float2 bb = *(const float2*)(sb2 + n0);
                    const float2 f0 = __ldg((const float2*)(fcorr + (size_t)j0 * 64 + n0));
                    const float2 f1 = __ldg((const float2*)(fcorr + (size_t)j1 * 64 + n0));
                    uint2 lo, hi;
                    lo.x = __float_as_uint(f0.x * gelu_f(acc[m][nt][0] + bb.x));
                    lo.y = __float_as_uint(f0.y * gelu_f(acc[m][nt][1] + bb.y));
                    hi.x = __float_as_uint(f1.x * gelu_f(acc[m][nt][2] + bb.x));
                    hi.y = __float_as_uint(f1.y * gelu_f(acc[m][nt][3] + bb.y));
                    *(uint2*)(A0 + e0 * STR0 + n0) = lo;
                    *(uint2*)(A0 + e1 * STR0 + n0) = hi;
                }
            }
        }
        GBAR();

        // ---- stage 3: U = obs_h * gelu(T @ Wrr + brr) -> A1   (K=64, N=128) ----
        {
            float acc[2][4][4];
            #pragma unroll
            for (int m = 0; m < 2; m++)
                #pragma unroll
                for (int nt = 0; nt < 4; nt++)
                    { acc[m][nt][0]=0.f; acc[m][nt][1]=0.f; acc[m][nt][2]=0.f; acc[m][nt][3]=0.f; }
            #pragma unroll
            for (int m = 0; m < 2; m++) {
                const uint32_t ab = A0u + (((m * 16 + rowoff) * STR0 + coloff) << 2);
                #pragma unroll
                for (int ks = 0; ks < 8; ks++) {
                    uint32_t a0, a1, a2, a3;
                    ldsm4(a0, a1, a2, a3, ab + ks * 32);
                    #pragma unroll
                    for (int nt = 0; nt < 4; nt++) {
                        const uint2 b = *(const uint2*)(Wrrf + (((wl*4+nt)*8+ks)<<6) + lane*2);
                        mma8(acc[m][nt], a0, a1, a2, a3, b.x, b.y);
                    }
                }
            }
            #pragma unroll
            for (int m = 0; m < 2; m++) {
                const int e0 = m * 16 + r, e1 = e0 + 8;
                const size_t o0 = (size_t)sObs[e0] * 128;
                const size_t o1 = (size_t)sObs[e1] * 128;
                #pragma unroll
                for (int nt = 0; nt < 4; nt++) {
                    const int n0 = (wl * 4 + nt) * 8 + 2 * q;
                    const float2 bb = *(const float2*)(sbrr + n0);
                    const float2 v0 = __ldg((const float2*)(obsE + o0 + n0));
                    const float2 v1 = __ldg((const float2*)(obsE + o1 + n0));
                    uint2 lo, hi;
                    lo.x = __float_as_uint(v0.x * gelu_f(acc[m][nt][0] + bb.x));
                    lo.y = __float_as_uint(v0.y * gelu_f(acc[m][nt][1] + bb.y));
                    hi.x = __float_as_uint(v1.x * gelu_f(acc[m][nt][2] + bb.x));
                    hi.y = __float_as_uint(v1.y * gelu_f(acc[m][nt][3] + bb.y));
                    *(uint2*)(A1 + e0 * STR1 + n0) = lo;
                    *(uint2*)(A1 + e1 * STR1 + n0) = hi;
                }
            }
        }
        GBAR();

        // ---- stage 4: out = gelu(U @ Wrc + brc) -> global   (K=128, N=128) ----
        {
            float acc[2][4][4];
            #pragma unroll
            for (int m = 0; m < 2; m++)
                #pragma unroll
                for (int nt = 0; nt < 4; nt++)
                    { acc[m][nt][0]=0.f; acc[m][nt][1]=0.f; acc[m][nt][2]=0.f; acc[m][nt][3]=0.f; }
            #pragma unroll
            for (int m = 0; m < 2; m++) {
                const uint32_t ab = A1u + (((m * 16 + rowoff) * STR1 + coloff) << 2);
                #pragma unroll
                for (int ks = 0; ks < 16; ks++) {
                    uint32_t a0, a1, a2, a3;
                    ldsm4(a0, a1, a2, a3, ab + ks * 32);
                    #pragma unroll
                    for (int nt = 0; nt < 4; nt++) {
                        const uint2 b = *(const uint2*)(Wrcf + (((wl*4+nt)*16+ks)<<6) + lane*2);
                        mma8(acc[m][nt], a0, a1, a2, a3, b.x, b.y);
                    }
                }
            }
            #pragma unroll
            for (int m = 0; m < 2; m++) {
                const int e0 = m * 16 + r, e1 = e0 + 8;
                float* o0 = out + (size_t)(base + e0) * 128;
                float* o1 = out + (size_t)(base + e1) * 128;
                #pragma unroll
                for (int nt = 0; nt < 4; nt++) {
                    const int n0 = (wl * 4 + nt) * 8 + 2 * q;
                    const float2 bb = *(const float2*)(sbrc + n0);
                    if (e0 < n_e) {
                        float2 v;
                        v.x = gelu_f(acc[m][nt][0] + bb.x);
                        v.y = gelu_f(acc[m][nt][1] + bb.y);
                        *(float2*)(o0 + n0) = v;
                    }
                    if (e1 < n_e) {
                        float2 v;
                        v.x = gelu_f(acc[m][nt][2] + bb.x);
                        v.y = gelu_f(acc[m][nt][3] + bb.y);
                        *(float2*)(o1 + n0) = v;
                    }
                }
            }
        }
        GBAR();   // protects A0/sObs/sJ before next tile's stage 0
    }
}

extern "C" void kernel_launch(void* const* d_in, const int* in_sizes, int n_in,
                              void* d_out, int out_size) {
    const float* known_mask   = (const float*)d_in[0];
    const int*   obs_idx      = (const int*)  d_in[1];
    const int*   obs_mask_idx = (const int*)  d_in[2];
    const int*   attr_idx     = (const int*)  d_in[3];
    const float* obs_embs     = (const float*)d_in[4];
    const float* fea_corr     = (const float*)d_in[5];
    const float* W1  = (const float*)d_in[6];
    const float* b1  = (const float*)d_in[7];
    const float* W2  = (const float*)d_in[8];
    const float* b2  = (const float*)d_in[9];
    const float* Wrr = (const float*)d_in[10];
    const float* brr = (const float*)d_in[11];
    const float* Wrc = (const float*)d_in[12];
    const float* brc = (const float*)d_in[13];
    const int E = in_sizes[1];

    int sms = 148;
    cudaDeviceGetAttribute(&sms, cudaDevAttrMultiProcessorCount, 0);
    cudaFuncSetAttribute(attr_rel_mma,
                         cudaFuncAttributeMaxDynamicSharedMemorySize, SMEM_BYTES);

    attr_rel_mma<<<sms, NTHREADS, SMEM_BYTES>>>(
        known_mask, obs_idx, obs_mask_idx, attr_idx, obs_embs, fea_corr,
        W1, b1, W2, b2, Wrr, brr, Wrc, brc,
        (float*)d_out, E);
}

// round 11
// speedup vs baseline: 3.1131x; 1.2154x over previous
#include <cuda_runtime.h>
#include <math.h>
#include <stdint.h>

#define NTHREADS 384
#define NGROUPS  3
#define TILE_E   32          // edges per group-tile

// fragment-ordered tf32 weights in device-global scratch (L1/L2-cached)
#define W1F_OFF   0
#define W2F_OFF   8192
#define WRRF_OFF  16384
#define WRCF_OFF  24576
__device__ uint32_t g_Wf[40960];

// ---------------- smem layout (bytes): activations only ----------------
#define OFF_A0    0                       // 3 x (32 x 68 f)  = 26112
#define OFF_A1    26112                   // 3 x (32 x 132 f) = 50688
#define OFF_B1    76800                   // 128 f
#define OFF_B2    77312                   // 64 f
#define OFF_BRR   77568                   // 128 f
#define OFF_BRC   78080                   // 128 f
#define OFF_OBS   78592                   // 3 x 32 int
#define OFF_J     78976                   // 3 x 32 int
#define SMEM_BYTES 79360

#define STR0 68    // word stride, A0: rows 4 banks apart -> LDSM conflict-free
#define STR1 132   // word stride, A1

// Fast exact-GELU: erf via Abramowitz-Stegun 7.1.26 (|eps| <= 1.5e-7)
__device__ __forceinline__ float gelu_f(float x) {
    const float ax = fabsf(x);
    const float z  = ax * 0.70710678118654752f;
    const float den = fmaf(0.3275911f, z, 1.0f);
    float t;
    asm("rcp.approx.f32 %0, %1;" : "=f"(t) : "f"(den));
    float p = fmaf(t, 1.061405429f, -1.453152027f);
    p = fmaf(t, p, 1.421413741f);
    p = fmaf(t, p, -0.284496736f);
    p = fmaf(t, p, 0.254829592f);
    p = p * t;
    const float e = __expf(-z * z);
    const float erfz = fmaf(-e, p, 1.0f);
    return fmaf(0.5f * ax, erfz, 0.5f * x);
}

__device__ __forceinline__ uint32_t f2tf(float x) {
    uint32_t r;
    asm("cvt.rna.tf32.f32 %0, %1;" : "=r"(r) : "f"(x));
    return r;
}

__device__ __forceinline__ void mma8(float d[4], uint32_t a0, uint32_t a1,
                                     uint32_t a2, uint32_t a3,
                                     uint32_t b0, uint32_t b1) {
    asm volatile(
        "mma.sync.aligned.m16n8k8.row.col.f32.tf32.tf32.f32 "
        "{%0,%1,%2,%3}, {%4,%5,%6,%7}, {%8,%9}, {%0,%1,%2,%3};"
        : "+f"(d[0]), "+f"(d[1]), "+f"(d[2]), "+f"(d[3])
        : "r"(a0), "r"(a1), "r"(a2), "r"(a3), "r"(b0), "r"(b1));
}

__device__ __forceinline__ void ldsm4(uint32_t& a0, uint32_t& a1,
                                      uint32_t& a2, uint32_t& a3, uint32_t addr) {
    asm volatile("ldmatrix.sync.aligned.m8n8.x4.shared.b16 {%0,%1,%2,%3}, [%4];"
                 : "=r"(a0), "=r"(a1), "=r"(a2), "=r"(a3) : "r"(addr));
}

#define GBAR() asm volatile("bar.sync %0, 128;" :: "r"(grp + 1) : "memory")

// one element of W [K,N] row-major -> tf32 B-fragment order
__device__ __forceinline__ void pf1(const float* __restrict__ W, int K, int N,
                                    uint32_t* __restrict__ dst, int j) {
    const int K8 = K >> 3;
    const int reg  = j & 1;
    const int lane = (j >> 1) & 31;
    const int fk   = j >> 6;
    const int ks   = fk % K8;
    const int nt   = fk / K8;
    const int k = ks * 8 + (lane & 3) + reg * 4;
    const int n = nt * 8 + (lane >> 2);
    dst[j] = f2tf(W[k * N + n]);
}

__global__ void prep_weights(const float* __restrict__ W1, const float* __restrict__ W2,
                             const float* __restrict__ Wrr, const float* __restrict__ Wrc) {
    int i = blockIdx.x * blockDim.x + threadIdx.x;
    for (; i < 40960; i += gridDim.x * blockDim.x) {
        if (i < 8192)       pf1(W1,   64, 128, g_Wf + W1F_OFF,  i);
        else if (i < 16384) pf1(W2,  128,  64, g_Wf + W2F_OFF,  i - 8192);
        else if (i < 24576) pf1(Wrr,  64, 128, g_Wf + WRRF_OFF, i - 16384);
        else                pf1(Wrc, 128, 128, g_Wf + WRCF_OFF, i - 24576);
    }
}

__global__ void __launch_bounds__(NTHREADS, 1)
attr_rel_mma(const float* __restrict__ km,  const int* __restrict__ obsI,
             const int* __restrict__ omI,   const int* __restrict__ atI,
             const float* __restrict__ obsE, const float* __restrict__ fcorr,
             const float* __restrict__ b1,  const float* __restrict__ b2,
             const float* __restrict__ brr, const float* __restrict__ brc,
             float* __restrict__ out, int E)
{
    extern __shared__ char smem[];
    float* sb1  = (float*)(smem + OFF_B1);
    float* sb2  = (float*)(smem + OFF_B2);
    float* sbrr = (float*)(smem + OFF_BRR);
    float* sbrc = (float*)(smem + OFF_BRC);

    const int tid  = threadIdx.x;
    const int warp = tid >> 5;
    const int lane = tid & 31;
    const int grp  = warp >> 2;          // work-group 0..2
    const int wl   = warp & 3;           // N-group within work-group
    const int tg   = tid & 127;          // thread id within group
    const int r    = lane >> 2;
    const int q    = lane & 3;

    uint32_t* A0 = (uint32_t*)(smem + OFF_A0) + grp * (TILE_E * STR0);
    uint32_t* A1 = (uint32_t*)(smem + OFF_A1) + grp * (TILE_E * STR1);
    int* sObs = (int*)(smem + OFF_OBS) + grp * TILE_E;
    int* sJ   = (int*)(smem + OFF_J)   + grp * TILE_E;

    const uint32_t A0u = (uint32_t)__cvta_generic_to_shared(A0);
    const uint32_t A1u = (uint32_t)__cvta_generic_to_shared(A1);
    const int rowoff = (lane & 7) + ((lane >> 3) & 1) * 8;
    const int coloff = (lane >> 4) << 2;

    const uint32_t* W1f  = g_Wf + W1F_OFF;
    const uint32_t* W2f  = g_Wf + W2F_OFF;
    const uint32_t* Wrrf = g_Wf + WRRF_OFF;
    const uint32_t* Wrcf = g_Wf + WRCF_OFF;

    for (int i = tid; i < 128; i += NTHREADS) sb1[i]  = b1[i];
    for (int i = tid; i < 64;  i += NTHREADS) sb2[i]  = b2[i];
    for (int i = tid; i < 128; i += NTHREADS) sbrr[i] = brr[i];
    for (int i = tid; i < 128; i += NTHREADS) sbrc[i] = brc[i];
    __syncthreads();

    const int ntiles = (E + TILE_E - 1) / TILE_E;

    for (int tile = blockIdx.x * NGROUPS + grp; tile < ntiles; tile += gridDim.x * NGROUPS) {
        const int base = tile * TILE_E;
        const int n_e  = min(TILE_E, E - base);

        // ---- stage 0: X = softmax(m_i*m_j) closed form -> A0 ----
        {
            const int e  = tg >> 2;
            const int qq = tg & 3;
            const int eg = base + (e < n_e ? e : n_e - 1);
            const int mrowi = omI[eg];
            const int jj    = atI[eg];
            if (qq == 0) { sObs[e] = obsI[eg]; sJ[e] = jj; }
            const float* mrow = km + (size_t)mrowi * 64;
            float mv[16];
            float s = 0.f;
            #pragma unroll
            for (int t = 0; t < 4; t++) {
                float4 v = *(const float4*)(mrow + qq * 16 + t * 4);
                mv[t*4+0]=v.x; mv[t*4+1]=v.y; mv[t*4+2]=v.z; mv[t*4+3]=v.w;
                s += v.x + v.y + v.z + v.w;
            }
            s += __shfl_xor_sync(0xffffffffu, s, 1);
            s += __shfl_xor_sync(0xffffffffu, s, 2);
            const float kn = s - mrow[jj];
            const float EU = 2.71828182845904523536f;
            const float alpha = 1.f / (kn * EU + (64.f - kn));
            const uint32_t ua = f2tf(alpha);
            const uint32_t ub = f2tf(EU * alpha);
            uint32_t w[16];
            #pragma unroll
            for (int t = 0; t < 16; t++) {
                const int f = qq * 16 + t;
                w[t] = (mv[t] != 0.f && f != jj) ? ub : ua;
            }
            uint4* dst = (uint4*)(A0 + e * STR0 + qq * 16);
            dst[0] = make_uint4(w[0],  w[1],  w[2],  w[3]);
            dst[1] = make_uint4(w[4],  w[5],  w[6],  w[7]);
            dst[2] = make_uint4(w[8],  w[9],  w[10], w[11]);
            dst[3] = make_uint4(w[12], w[13], w[14], w[15]);
        }
        GBAR();

        // ---- stage 1: H = gelu(X @ W1 + b1) -> A1   (K=64, N=128) ----
        {
            float acc[2][4][4];
            #pragma unroll
            for (int m = 0; m < 2; m++)
                #pragma unroll
                for (int nt = 0; nt < 4; nt++)
                    { acc[m][nt][0]=0.f; acc[m][nt][1]=0.f; acc[m][nt][2]=0.f; acc[m][nt][3]=0.f; }
            #pragma unroll
            for (int m = 0; m < 2; m++) {
                const uint32_t ab = A0u + (((m * 16 + rowoff) * STR0 + coloff) << 2);
                #pragma unroll
                for (int ks = 0; ks < 8; ks++) {
                    uint32_t a0, a1, a2, a3;
                    ldsm4(a0, a1, a2, a3, ab + ks * 32);
                    #pragma unroll
                    for (int nt = 0; nt < 4; nt++) {
                        const uint2 b = __ldg((const uint2*)(W1f + (((wl*4+nt)*8+ks)<<6) + lane*2));
                        mma8(acc[m][nt], a0, a1, a2, a3, b.x, b.y);
                    }
                }
            }
            #pragma unroll
            for (int m = 0; m < 2; m++) {
                const int e0 = m * 16 + r;
                #pragma unroll
                for (int nt = 0; nt < 4; nt++) {
                    const int n0 = (wl * 4 + nt) * 8 + 2 * q;
                    const float2 bb = *(const float2*)(sb1 + n0);
                    uint2 lo, hi;
                    lo.x = __float_as_uint(gelu_f(acc[m][nt][0] + bb.x));
                    lo.y = __float_as_uint(gelu_f(acc[m][nt][1] + bb.y));
                    hi.x = __float_as_uint(gelu_f(acc[m][nt][2] + bb.x));
                    hi.y = __float_as_uint(gelu_f(acc[m][nt][3] + bb.y));
                    *(uint2*)(A1 + e0 * STR1 + n0)       = lo;
                    *(uint2*)(A1 + (e0 + 8) * STR1 + n0) = hi;
                }
            }
        }
        GBAR();

        // ---- stage 2: T = fea_corr[j] * gelu(H @ W2 + b2) -> A0   (K=128, N=64) ----
        {
            float acc[2][2][4];
            #pragma unroll
            for (int m = 0; m < 2; m++)
                #pragma unroll
                for (int nt = 0; nt < 2; nt++)
                    { acc[m][nt][0]=0.f; acc[m][nt][1]=0.f; acc[m][nt][2]=0.f; acc[m][nt][3]=0.f; }
            #pragma unroll
            for (int m = 0; m < 2; m++) {
                const uint32_t ab = A1u + (((m * 16 + rowoff) * STR1 + coloff) << 2);
                #pragma unroll
                for (int ks = 0; ks < 16; ks++) {
                    uint32_t a0, a1, a2, a3;
                    ldsm4(a0, a1, a2, a3, ab + ks * 32);
                    #pragma unroll
                    for (int nt = 0; nt < 2; nt++) {
                        const uint2 b = __ldg((const uint2*)(W2f + (((wl*2+nt)*16+ks)<<6) + lane*2));
                        mma8(acc[m][nt], a0, a1, a2, a3, b.x, b.y);
                    }
                }
            }
            #pragma unroll
            for (int m = 0; m < 2; m++) {
                const int e0 = m * 16 + r, e1 = e0 + 8;
                const int j0 = sJ[e0], j1 = sJ[e1];
                #pragma unroll
                for (int nt = 0; nt < 2; nt++) {
                    const int n0 = (wl * 2 + nt) * 8 + 2 * q;
                    const float2 bb = *(const float2*)(sb2 + n0);
                    const float2 f0 = __ldg((const float2*)(fcorr + (size_t)j0 * 64 + n0));
                    const float2 f1 = __ldg((const float2*)(fcorr + (size_t)j1 * 64 + n0));
                    uint2 lo, hi;
                    lo.x = __float_as_uint(f0.x * gelu_f(acc[m][nt][0] + bb.x));
                    lo.y = __float_as_uint(f0.y * gelu_f(acc[m][nt][1] + bb.y));
                    hi.x = __float_as_uint(f1.x * gelu_f(acc[m][nt][2] + bb.x));
                    hi.y = __float_as_uint(f1.y * gelu_f(acc[m][nt][3] + bb.y));
                    *(uint2*)(A0 + e0 * STR0 + n0) = lo;
                    *(uint2*)(A0 + e1 * STR0 + n0) = hi;
                }
            }
        }
        GBAR();

        // ---- stage 3: U = obs_h * gelu(T @ Wrr + brr) -> A1   (K=64, N=128) ----
        {
            float acc[2][4][4];
            #pragma unroll
            for (int m = 0; m < 2; m++)
                #pragma unroll
                for (int nt = 0; nt < 4; nt++)
                    { acc[m][nt][0]=0.f; acc[m][nt][1]=0.f; acc[m][nt][2]=0.f; acc[m][nt][3]=0.f; }
            #pragma unroll
            for (int m = 0; m < 2; m++) {
                const uint32_t ab = A0u + (((m * 16 + rowoff) * STR0 + coloff) << 2);
                #pragma unroll
                for (int ks = 0; ks < 8; ks++) {
                    uint32_t a0, a1, a2, a3;
                    ldsm4(a0, a1, a2, a3, ab + ks * 32);
                    #pragma unroll
                    for (int nt = 0; nt < 4; nt++) {
                        const uint2 b = __ldg((const uint2*)(Wrrf + (((wl*4+nt)*8+ks)<<6) + lane*2));
                        mma8(acc[m][nt], a0, a1, a2, a3, b.x, b.y);
                    }
                }
            }
            #pragma unroll
            for (int m = 0; m < 2; m++) {
                const int e0 = m * 16 + r, e1 = e0 + 8;
                const size_t o0 = (size_t)sObs[e0] * 128;
                const size_t o1 = (size_t)sObs[e1] * 128;
                #pragma unroll
                for (int nt = 0; nt < 4; nt++) {
                    const int n0 = (wl * 4 + nt) * 8 + 2 * q;
                    const float2 bb = *(const float2*)(sbrr + n0);
                    const float2 v0 = __ldg((const float2*)(obsE + o0 + n0));
                    const float2 v1 = __ldg((const float2*)(obsE + o1 + n0));
                    uint2 lo, hi;
                    lo.x = __float_as_uint(v0.x * gelu_f(acc[m][nt][0] + bb.x));
                    lo.y = __float_as_uint(v0.y * gelu_f(acc[m][nt][1] + bb.y));
                    hi.x = __float_as_uint(v1.x * gelu_f(acc[m][nt][2] + bb.x));
                    hi.y = __float_as_uint(v1.y * gelu_f(acc[m][nt][3] + bb.y));
                    *(uint2*)(A1 + e0 * STR1 + n0) = lo;
                    *(uint2*)(A1 + e1 * STR1 + n0) = hi;
                }
            }
        }
        GBAR();

        // ---- stage 4: out = gelu(U @ Wrc + brc) -> global   (K=128, N=128) ----
        {
            float acc[2][4][4];
            #pragma unroll
            for (int m = 0; m < 2; m++)
                #pragma unroll
                for (int nt = 0; nt < 4; nt++)
                    { acc[m][nt][0]=0.f; acc[m][nt][1]=0.f; acc[m][nt][2]=0.f; acc[m][nt][3]=0.f; }
            #pragma unroll
            for (int m = 0; m < 2; m++) {
                const uint32_t ab = A1u + (((m * 16 + rowoff) * STR1 + coloff) << 2);
                #pragma unroll
                for (int ks = 0; ks < 16; ks++) {
                    uint32_t a0, a1, a2, a3;
                    ldsm4(a0, a1, a2, a3, ab + ks * 32);
                    #pragma unroll
                    for (int nt = 0; nt < 4; nt++) {
                        const uint2 b = __ldg((const uint2*)(Wrcf + (((wl*4+nt)*16+ks)<<6) + lane*2));
                        mma8(acc[m][nt], a0, a1, a2, a3, b.x, b.y);
                    }
                }
            }
            #pragma unroll
            for (int m = 0; m < 2; m++) {
                const int e0 = m * 16 + r, e1 = e0 + 8;
                float* o0 = out + (size_t)(base + e0) * 128;
                float* o1 = out + (size_t)(base + e1) * 128;
                #pragma unroll
                for (int nt = 0; nt < 4; nt++) {
                    const int n0 = (wl * 4 + nt) * 8 + 2 * q;
                    const float2 bb = *(const float2*)(sbrc + n0);
                    if (e0 < n_e) {
                        float2 v;
                        v.x = gelu_f(acc[m][nt][0] + bb.x);
                        v.y = gelu_f(acc[m][nt][1] + bb.y);
                        *(float2*)(o0 + n0) = v;
                    }
                    if (e1 < n_e) {
                        float2 v;
                        v.x = gelu_f(acc[m][nt][2] + bb.x);
                        v.y = gelu_f(acc[m][nt][3] + bb.y);
                        *(float2*)(o1 + n0) = v;
                    }
                }
            }
        }
        GBAR();   // protects A0/sObs/sJ before next tile's stage 0
    }
}

extern "C" void kernel_launch(void* const* d_in, const int* in_sizes, int n_in,
                              void* d_out, int out_size) {
    const float* known_mask   = (const float*)d_in[0];
    const int*   obs_idx      = (const int*)  d_in[1];
    const int*   obs_mask_idx = (const int*)  d_in[2];
    const int*   attr_idx     = (const int*)  d_in[3];
    const float* obs_embs     = (const float*)d_in[4];
    const float* fea_corr     = (const float*)d_in[5];
    const float* W1  = (const float*)d_in[6];
    const float* b1  = (const float*)d_in[7];
    const float* W2  = (const float*)d_in[8];
    const float* b2  = (const float*)d_in[9];
    const float* Wrr = (const float*)d_in[10];
    const float* brr = (const float*)d_in[11];
    const float* Wrc = (const float*)d_in[12];
    const float* brc = (const float*)d_in[13];
    const int E = in_sizes[1];

    int sms = 148;
    cudaDeviceGetAttribute(&sms, cudaDevAttrMultiProcessorCount, 0);
    cudaFuncSetAttribute(attr_rel_mma,
                         cudaFuncAttributeMaxDynamicSharedMemorySize, SMEM_BYTES);

    prep_weights<<<160, 256>>>(W1, W2, Wrr, Wrc);
    attr_rel_mma<<<sms, NTHREADS, SMEM_BYTES>>>(
        known_mask, obs_idx, obs_mask_idx, attr_idx, obs_embs, fea_corr,
        b1, b2, brr, brc,
        (float*)d_out, E);
}